// round 6
// baseline (speedup 1.0000x reference)
#include <cuda_runtime.h>
#include <math.h>
#include <float.h>
#include <stdint.h>

#define NN    20000
#define TT    30
#define INDIM 32
#define HDIM  64
#define GDIM  256          // 4*H
#define MAXE  524288

// ---------------- scratch (device globals; no allocation allowed) ----------------
static __device__ float g_h0seq[(size_t)NN * TT * HDIM];   // layer0 hidden sequence
static __device__ float g_hlast[NN * HDIM];
static __device__ float g_hfeat1[NN * GDIM];
static __device__ float g_out1[NN * GDIM];                 // relu(gat1 + b1)
static __device__ float g_hfeat2[NN * 32];
static __device__ float g_asrc1[NN * 4], g_adst1[NN * 4];
static __device__ float g_asrc2[NN], g_adst2[NN];
static __device__ int   g_src[MAXE], g_dst[MAXE];
static __device__ int   g_colidx[MAXE + NN];
static __device__ int   g_rowptr[NN + 1];
static __device__ int   g_cursor[NN];
static __device__ int   g_counts[NN];
static __device__ int   g_is64;

// ---------------- helpers ----------------
__device__ __forceinline__ float lrelu(float x) { return x > 0.f ? x : 0.2f * x; }
__device__ __forceinline__ float sigm(float x)  { return 1.f / (1.f + expf(-x)); }

__device__ __forceinline__ float warp_max(float v) {
#pragma unroll
    for (int o = 16; o > 0; o >>= 1) v = fmaxf(v, __shfl_xor_sync(0xffffffffu, v, o));
    return v;
}
__device__ __forceinline__ float warp_sum(float v) {
#pragma unroll
    for (int o = 16; o > 0; o >>= 1) v += __shfl_xor_sync(0xffffffffu, v, o);
    return v;
}

// ---------------- edge dtype handling ----------------
__global__ void detect_kernel(const int* __restrict__ w, int E) {
    if (blockIdx.x == 0 && threadIdx.x == 0) {
        int n = E < 64 ? E : 64;
        int f = 1;
        for (int i = 0; i < n; i++)
            if (w[2 * i + 1] != 0) f = 0;   // int64 node ids < 2^31 => high words all 0
        g_is64 = f;
    }
}

__global__ void norm_kernel(const int* __restrict__ w, int E) {
    int e = blockIdx.x * blockDim.x + threadIdx.x;
    if (e >= E) return;
    if (g_is64) {
        g_src[e] = w[2 * e];
        g_dst[e] = w[2 * (E + e)];
    } else {
        g_src[e] = w[e];
        g_dst[e] = w[E + e];
    }
}

// ---------------- CSR build (dst-grouped, self-loop first) ----------------
__global__ void init_counts_kernel() {
    int i = blockIdx.x * blockDim.x + threadIdx.x;
    if (i < NN) g_counts[i] = 1;           // self loop
}
__global__ void count_kernel(int E) {
    int e = blockIdx.x * blockDim.x + threadIdx.x;
    if (e < E) atomicAdd(&g_counts[g_dst[e]], 1);
}
__global__ void scan_kernel() {
    __shared__ int part[1024];
    const int CH = 20;                     // 1024*20 >= 20000
    int tid = threadIdx.x;
    int b = tid * CH;
    int s = 0;
    for (int i = 0; i < CH; i++)
        if (b + i < NN) s += g_counts[b + i];
    part[tid] = s;
    __syncthreads();
    for (int off = 1; off < 1024; off <<= 1) {
        int v = (tid >= off) ? part[tid - off] : 0;
        __syncthreads();
        part[tid] += v;
        __syncthreads();
    }
    int run = part[tid] - s;               // exclusive prefix
    for (int i = 0; i < CH; i++)
        if (b + i < NN) { g_rowptr[b + i] = run; run += g_counts[b + i]; }
    if (tid == 1023) g_rowptr[NN] = part[1023];
}
__global__ void selfloop_kernel() {
    int d = blockIdx.x * blockDim.x + threadIdx.x;
    if (d >= NN) return;
    int p = g_rowptr[d];
    g_colidx[p] = d;
    g_cursor[d] = p + 1;
}
__global__ void fill_kernel(int E) {
    int e = blockIdx.x * blockDim.x + threadIdx.x;
    if (e >= E) return;
    int d = g_dst[e];
    int p = atomicAdd(&g_cursor[d], 1);
    g_colidx[p] = g_src[e];
}

// ---------------- fused LSTM layer ----------------
// 32 batch rows per CTA, 256 threads. smem: combined weights [K][256],
// bias[256], transposed activations inb[K][33], gate buffer gsm[32][256].
template<int LAYER>
__global__ void __launch_bounds__(256, 1)
lstm_kernel(const float* __restrict__ xin,
            const float* __restrict__ Wih, const float* __restrict__ Whh,
            const float* __restrict__ bih, const float* __restrict__ bhh)
{
    constexpr int D = (LAYER == 0) ? INDIM : HDIM;
    constexpr int K = D + HDIM;
    const float* src = (LAYER == 0) ? xin : g_h0seq;
    float* dst = (LAYER == 0) ? g_h0seq : g_hlast;

    extern __shared__ float sm[];
    float* Wc   = sm;                    // K*256
    float* bias = Wc + K * GDIM;         // 256
    float* inb  = bias + GDIM;           // K*33 (transposed input/hidden)
    float* gsm  = inb + K * 33;          // 32*256

    const int tid  = threadIdx.x;
    const int row0 = blockIdx.x * 32;

    for (int idx = tid; idx < D * GDIM;    idx += 256) Wc[idx] = Wih[idx];
    for (int idx = tid; idx < HDIM * GDIM; idx += 256) Wc[D * GDIM + idx] = Whh[idx];
    for (int idx = tid; idx < GDIM;        idx += 256) bias[idx] = bih[idx] + bhh[idx];
    for (int idx = tid; idx < HDIM * 33;   idx += 256) inb[D * 33 + idx] = 0.f;  // h=0

    float c[8];
#pragma unroll
    for (int p = 0; p < 8; p++) c[p] = 0.f;

    const int er  = tid >> 3;            // elementwise row 0..31
    const int eu0 = (tid & 7) << 3;      // elementwise unit base
    const int rg  = tid >> 5;            // gemm row group (warp)
    const int cg  = tid & 31;            // gemm col lane

    __syncthreads();

    for (int t = 0; t < TT; t++) {
        // stage x_t transposed: inb[k][r]
        for (int idx = tid; idx < 32 * D; idx += 256) {
            int r = idx / D, k = idx - r * D;
            inb[k * 33 + r] = src[((size_t)(row0 + r) * TT + t) * D + k];
        }
        __syncthreads();

        // GEMM: g[r][j] = sum_k inb[k][r] * Wc[k][j], 4 rows x 8 strided cols / thread
        float acc[4][8];
#pragma unroll
        for (int i = 0; i < 4; i++)
#pragma unroll
            for (int m = 0; m < 8; m++) acc[i][m] = 0.f;

#pragma unroll 4
        for (int k = 0; k < K; k++) {
            float a0 = inb[k * 33 + (rg << 2) + 0];
            float a1 = inb[k * 33 + (rg << 2) + 1];
            float a2 = inb[k * 33 + (rg << 2) + 2];
            float a3 = inb[k * 33 + (rg << 2) + 3];
#pragma unroll
            for (int m = 0; m < 8; m++) {
                float w = Wc[k * GDIM + cg + (m << 5)];
                acc[0][m] += a0 * w;
                acc[1][m] += a1 * w;
                acc[2][m] += a2 * w;
                acc[3][m] += a3 * w;
            }
        }
#pragma unroll
        for (int i = 0; i < 4; i++)
#pragma unroll
            for (int m = 0; m < 8; m++)
                gsm[((rg << 2) + i) * GDIM + cg + (m << 5)] = acc[i][m];
        __syncthreads();

        // elementwise LSTM cell: this thread owns (row er, units eu0..eu0+7)
#pragma unroll
        for (int p = 0; p < 8; p++) {
            int u = eu0 + p;
            float gi = gsm[er * GDIM + u]         + bias[u];
            float gf = gsm[er * GDIM + 64  + u]   + bias[64 + u];
            float gc = gsm[er * GDIM + 128 + u]   + bias[128 + u];
            float go = gsm[er * GDIM + 192 + u]   + bias[192 + u];
            float iv = sigm(gi), fv = sigm(gf), ov = sigm(go);
            float cv = tanhf(gc);
            c[p] = fv * c[p] + iv * cv;
            float hv = ov * tanhf(c[p]);
            inb[(D + u) * 33 + er] = hv;
            if (LAYER == 0)
                dst[((size_t)(row0 + er) * TT + t) * HDIM + u] = hv;
            else if (t == TT - 1)
                dst[(size_t)(row0 + er) * HDIM + u] = hv;
        }
        __syncthreads();
    }
}

// ---------------- GAT1 feature GEMM: hlast(N,64) @ W1(64,256) ----------------
__global__ void __launch_bounds__(256) gemm1_kernel(const float* __restrict__ W1) {
    __shared__ float hs[8 * 64];
    int tid = threadIdx.x;
    int n0 = blockIdx.x * 8;
    for (int idx = tid; idx < 8 * 64; idx += 256) hs[idx] = g_hlast[(size_t)n0 * 64 + idx];
    __syncthreads();
    int j = tid;
    float acc[8];
#pragma unroll
    for (int nn = 0; nn < 8; nn++) acc[nn] = 0.f;
    for (int k = 0; k < 64; k++) {
        float w = W1[k * 256 + j];
#pragma unroll
        for (int nn = 0; nn < 8; nn++) acc[nn] += w * hs[nn * 64 + k];
    }
#pragma unroll
    for (int nn = 0; nn < 8; nn++)
        g_hfeat1[(size_t)(n0 + nn) * 256 + j] = acc[nn];
}

__global__ void attn1_kernel(const float* __restrict__ as1, const float* __restrict__ ad1) {
    int idx = blockIdx.x * blockDim.x + threadIdx.x;
    if (idx >= NN * 4) return;
    int n = idx >> 2, hd = idx & 3;
    const float* hp = g_hfeat1 + (size_t)n * 256 + hd * 64;
    float ss = 0.f, sd = 0.f;
    for (int cix = 0; cix < 64; cix++) {
        float v = hp[cix];
        ss += v * as1[hd * 64 + cix];
        sd += v * ad1[hd * 64 + cix];
    }
    g_asrc1[idx] = ss;
    g_adst1[idx] = sd;
}

__device__ __forceinline__ void online_upd(float& m, float& s, float l) {
    if (l > m) { s = s * expf(m - l) + 1.f; m = l; }
    else       { s += expf(l - m); }
}

// ---------------- GAT1 gather: warp per node, softmax over incoming edges ----------------
__global__ void __launch_bounds__(256) gather1_kernel(const float* __restrict__ b1) {
    int warp = (blockIdx.x * blockDim.x + threadIdx.x) >> 5;
    int lane = threadIdx.x & 31;
    if (warp >= NN) return;
    int d = warp;
    int base = g_rowptr[d], end = g_rowptr[d + 1];

    float4 ad = *(const float4*)(g_adst1 + 4 * d);

    // pass 1: per-lane online max/sum per head, then warp combine
    float m0 = -FLT_MAX, m1 = -FLT_MAX, m2 = -FLT_MAX, m3 = -FLT_MAX;
    float s0 = 0.f, s1 = 0.f, s2 = 0.f, s3 = 0.f;
    for (int i = base + lane; i < end; i += 32) {
        int s = g_colidx[i];
        float4 av = *(const float4*)(g_asrc1 + 4 * s);
        online_upd(m0, s0, lrelu(av.x + ad.x));
        online_upd(m1, s1, lrelu(av.y + ad.y));
        online_upd(m2, s2, lrelu(av.z + ad.z));
        online_upd(m3, s3, lrelu(av.w + ad.w));
    }
    int hd_l = lane >> 3;
    float mh = 0.f, ish = 0.f, adl = 0.f;
    {
        float M, S;
        M = warp_max(m0); S = warp_sum(s0 * expf(m0 - M));
        if (hd_l == 0) { mh = M; ish = 1.f / S; adl = ad.x; }
        M = warp_max(m1); S = warp_sum(s1 * expf(m1 - M));
        if (hd_l == 1) { mh = M; ish = 1.f / S; adl = ad.y; }
        M = warp_max(m2); S = warp_sum(s2 * expf(m2 - M));
        if (hd_l == 2) { mh = M; ish = 1.f / S; adl = ad.z; }
        M = warp_max(m3); S = warp_sum(s3 * expf(m3 - M));
        if (hd_l == 3) { mh = M; ish = 1.f / S; adl = ad.w; }
    }

    // pass 2: weighted gather; lane owns channels [lane*8, lane*8+8)
    float acc[8];
#pragma unroll
    for (int q = 0; q < 8; q++) acc[q] = 0.f;
    for (int i = base; i < end; i++) {
        int s = g_colidx[i];
        float l = lrelu(g_asrc1[s * 4 + hd_l] + adl);
        float w = expf(l - mh) * ish;
        const float4* hp = (const float4*)(g_hfeat1 + (size_t)s * 256 + lane * 8);
        float4 u = hp[0], v = hp[1];
        acc[0] += w * u.x; acc[1] += w * u.y; acc[2] += w * u.z; acc[3] += w * u.w;
        acc[4] += w * v.x; acc[5] += w * v.y; acc[6] += w * v.z; acc[7] += w * v.w;
    }
    size_t ob = (size_t)d * 256 + lane * 8;
#pragma unroll
    for (int q = 0; q < 8; q++) {
        float o = acc[q] + b1[lane * 8 + q];
        g_out1[ob + q] = o > 0.f ? o : 0.f;   // relu folded for GAT2 input
    }
}

// ---------------- GAT2 feature GEMM: relu(out1)(N,256) @ W2(256,32) ----------------
__global__ void __launch_bounds__(256) gemm2_kernel(const float* __restrict__ W2) {
    __shared__ float W2s[256 * 32];   // 32 KB
    __shared__ float ins[16 * 256];   // 16 KB
    int tid = threadIdx.x;
    int n0 = blockIdx.x * 16;
    for (int idx = tid; idx < 256 * 32; idx += 256) W2s[idx] = W2[idx];
    for (int idx = tid; idx < 16 * 256; idx += 256) ins[idx] = g_out1[(size_t)n0 * 256 + idx];
    __syncthreads();
    int cix = tid & 31;
    int ng = tid >> 5;               // 0..7
    float acc[2] = {0.f, 0.f};
    for (int k = 0; k < 256; k++) {
        float w = W2s[k * 32 + cix];
        acc[0] += w * ins[ng * 256 + k];
        acc[1] += w * ins[(ng + 8) * 256 + k];
    }
    g_hfeat2[(size_t)(n0 + ng) * 32 + cix]     = acc[0];
    g_hfeat2[(size_t)(n0 + ng + 8) * 32 + cix] = acc[1];
}

__global__ void attn2_kernel(const float* __restrict__ as2, const float* __restrict__ ad2) {
    int n = blockIdx.x * blockDim.x + threadIdx.x;
    if (n >= NN) return;
    const float* hp = g_hfeat2 + (size_t)n * 32;
    float ss = 0.f, sd = 0.f;
    for (int cix = 0; cix < 32; cix++) {
        float v = hp[cix];
        ss += v * as2[cix];
        sd += v * ad2[cix];
    }
    g_asrc2[n] = ss;
    g_adst2[n] = sd;
}

__global__ void __launch_bounds__(256) gather2_kernel(const float* __restrict__ b2,
                                                      float* __restrict__ out) {
    int warp = (blockIdx.x * blockDim.x + threadIdx.x) >> 5;
    int lane = threadIdx.x & 31;
    if (warp >= NN) return;
    int d = warp;
    int base = g_rowptr[d], end = g_rowptr[d + 1];
    float adv = g_adst2[d];

    float m = -FLT_MAX, s = 0.f;
    for (int i = base + lane; i < end; i += 32) {
        int sidx = g_colidx[i];
        online_upd(m, s, lrelu(g_asrc2[sidx] + adv));
    }
    float M = warp_max(m);
    float S = warp_sum(s * expf(m - M));
    float ish = 1.f / S;

    float acc = 0.f;
    for (int i = base; i < end; i++) {
        int sidx = g_colidx[i];
        float l = lrelu(g_asrc2[sidx] + adv);
        float w = expf(l - M) * ish;
        acc += w * g_hfeat2[(size_t)sidx * 32 + lane];
    }
    out[(size_t)d * 32 + lane] = acc + b2[lane];
}

// ---------------- launch ----------------
extern "C" void kernel_launch(void* const* d_in, const int* in_sizes, int n_in,
                              void* d_out, int out_size) {
    const float* x     = (const float*)d_in[0];
    const int*   ei    = (const int*)d_in[1];
    const float* Wih0  = (const float*)d_in[2];
    const float* Whh0  = (const float*)d_in[3];
    const float* bih0  = (const float*)d_in[4];
    const float* bhh0  = (const float*)d_in[5];
    const float* Wih1  = (const float*)d_in[6];
    const float* Whh1  = (const float*)d_in[7];
    const float* bih1  = (const float*)d_in[8];
    const float* bhh1  = (const float*)d_in[9];
    const float* W1    = (const float*)d_in[10];
    const float* as1   = (const float*)d_in[11];
    const float* ad1   = (const float*)d_in[12];
    const float* b1    = (const float*)d_in[13];
    const float* W2    = (const float*)d_in[14];
    const float* as2   = (const float*)d_in[15];
    const float* ad2   = (const float*)d_in[16];
    const float* b2    = (const float*)d_in[17];
    float* out = (float*)d_out;

    int E = in_sizes[1] / 2;
    if (E > MAXE) E = MAXE;

    const int SMEM0 = (INDIM + HDIM) * GDIM * 4 + GDIM * 4 + (INDIM + HDIM) * 33 * 4 + 32 * GDIM * 4;
    const int SMEM1 = (HDIM + HDIM)  * GDIM * 4 + GDIM * 4 + (HDIM + HDIM)  * 33 * 4 + 32 * GDIM * 4;
    cudaFuncSetAttribute(lstm_kernel<0>, cudaFuncAttributeMaxDynamicSharedMemorySize, SMEM0);
    cudaFuncSetAttribute(lstm_kernel<1>, cudaFuncAttributeMaxDynamicSharedMemorySize, SMEM1);

    // edge normalization + CSR build
    detect_kernel<<<1, 32>>>(ei, E);
    norm_kernel<<<(E + 255) / 256, 256>>>(ei, E);
    init_counts_kernel<<<(NN + 255) / 256, 256>>>();
    count_kernel<<<(E + 255) / 256, 256>>>(E);
    scan_kernel<<<1, 1024>>>();
    selfloop_kernel<<<(NN + 255) / 256, 256>>>();
    fill_kernel<<<(E + 255) / 256, 256>>>(E);

    // LSTM stack
    lstm_kernel<0><<<NN / 32, 256, SMEM0>>>(x, Wih0, Whh0, bih0, bhh0);
    lstm_kernel<1><<<NN / 32, 256, SMEM1>>>(x, Wih1, Whh1, bih1, bhh1);

    // GAT layer 1
    gemm1_kernel<<<NN / 8, 256>>>(W1);
    attn1_kernel<<<(NN * 4 + 255) / 256, 256>>>(as1, ad1);
    gather1_kernel<<<(NN * 32 + 255) / 256, 256>>>(b1);

    // GAT layer 2
    gemm2_kernel<<<NN / 16, 256>>>(W2);
    attn2_kernel<<<(NN + 255) / 256, 256>>>(as2, ad2);
    gather2_kernel<<<(NN * 32 + 255) / 256, 256>>>(b2, out);

    (void)n_in; (void)out_size;
}

// round 7
// speedup vs baseline: 1.6844x; 1.6844x over previous
#include <cuda_runtime.h>
#include <math.h>
#include <float.h>
#include <stdint.h>

#define NN    20000
#define TT    30
#define INDIM 32
#define HDIM  64
#define GDIM  256          // 4*H
#define MAXE  524288

#define LROWS 72           // rows per LSTM CTA (8 warps x 9 rows)
#define LPAD  77           // row pitch in inb (odd-ish mod 32 for bank behavior)

// ---------------- scratch (device globals; no allocation allowed) ----------------
static __device__ float g_h0seq[(size_t)NN * TT * HDIM];   // layer0 hidden sequence
static __device__ float g_hlast[NN * HDIM];
static __device__ float g_hfeat1[NN * GDIM];
static __device__ float g_out1[NN * GDIM];                 // relu(gat1 + b1)
static __device__ float g_hfeat2[NN * 32];
static __device__ float g_asrc1[NN * 4], g_adst1[NN * 4];
static __device__ float g_asrc2[NN], g_adst2[NN];
static __device__ int   g_src[MAXE], g_dst[MAXE];
static __device__ int   g_colidx[MAXE + NN];
static __device__ int   g_rowptr[NN + 1];
static __device__ int   g_cursor[NN];
static __device__ int   g_counts[NN];
static __device__ int   g_is64;

// ---------------- helpers ----------------
__device__ __forceinline__ float lrelu(float x) { return x > 0.f ? x : 0.2f * x; }

// fast-but-accurate-enough activations (err ~1e-6 rel; budget is 1e-3)
__device__ __forceinline__ float sigm_f(float x)  { return __fdividef(1.f, 1.f + __expf(-x)); }
__device__ __forceinline__ float tanh_f(float x)  { return __fdividef(2.f, 1.f + __expf(-2.f * x)) - 1.f; }
__device__ __forceinline__ float sigm(float x)    { return 1.f / (1.f + expf(-x)); }

__device__ __forceinline__ float warp_max(float v) {
#pragma unroll
    for (int o = 16; o > 0; o >>= 1) v = fmaxf(v, __shfl_xor_sync(0xffffffffu, v, o));
    return v;
}
__device__ __forceinline__ float warp_sum(float v) {
#pragma unroll
    for (int o = 16; o > 0; o >>= 1) v += __shfl_xor_sync(0xffffffffu, v, o);
    return v;
}

// ---- f32x2 packed-math primitives (SASS FFMA2 is PTX-only) ----
__device__ __forceinline__ void ffma2(unsigned long long& d, unsigned long long a, unsigned long long b) {
    asm("fma.rn.f32x2 %0, %1, %2, %3;" : "=l"(d) : "l"(a), "l"(b), "l"(d));
}
__device__ __forceinline__ unsigned long long dup2(float v) {
    unsigned long long r;
    asm("mov.b64 %0, {%1, %1};" : "=l"(r) : "f"(v));
    return r;
}
__device__ __forceinline__ void unpk2(unsigned long long v, float& lo, float& hi) {
    asm("mov.b64 {%0, %1}, %2;" : "=f"(lo), "=f"(hi) : "l"(v));
}

// ---------------- edge dtype handling ----------------
__global__ void detect_kernel(const int* __restrict__ w, int E) {
    if (blockIdx.x == 0 && threadIdx.x == 0) {
        int n = E < 64 ? E : 64;
        int f = 1;
        for (int i = 0; i < n; i++)
            if (w[2 * i + 1] != 0) f = 0;   // int64 node ids < 2^31 => high words all 0
        g_is64 = f;
    }
}

__global__ void norm_kernel(const int* __restrict__ w, int E) {
    int e = blockIdx.x * blockDim.x + threadIdx.x;
    if (e >= E) return;
    if (g_is64) {
        g_src[e] = w[2 * e];
        g_dst[e] = w[2 * (E + e)];
    } else {
        g_src[e] = w[e];
        g_dst[e] = w[E + e];
    }
}

// ---------------- CSR build (dst-grouped, self-loop first) ----------------
__global__ void init_counts_kernel() {
    int i = blockIdx.x * blockDim.x + threadIdx.x;
    if (i < NN) g_counts[i] = 1;           // self loop
}
__global__ void count_kernel(int E) {
    int e = blockIdx.x * blockDim.x + threadIdx.x;
    if (e < E) atomicAdd(&g_counts[g_dst[e]], 1);
}
__global__ void scan_kernel() {
    __shared__ int part[1024];
    const int CH = 20;                     // 1024*20 >= 20000
    int tid = threadIdx.x;
    int b = tid * CH;
    int s = 0;
    for (int i = 0; i < CH; i++)
        if (b + i < NN) s += g_counts[b + i];
    part[tid] = s;
    __syncthreads();
    for (int off = 1; off < 1024; off <<= 1) {
        int v = (tid >= off) ? part[tid - off] : 0;
        __syncthreads();
        part[tid] += v;
        __syncthreads();
    }
    int run = part[tid] - s;               // exclusive prefix
    for (int i = 0; i < CH; i++)
        if (b + i < NN) { g_rowptr[b + i] = run; run += g_counts[b + i]; }
    if (tid == 1023) g_rowptr[NN] = part[1023];
}
__global__ void selfloop_kernel() {
    int d = blockIdx.x * blockDim.x + threadIdx.x;
    if (d >= NN) return;
    int p = g_rowptr[d];
    g_colidx[p] = d;
    g_cursor[d] = p + 1;
}
__global__ void fill_kernel(int E) {
    int e = blockIdx.x * blockDim.x + threadIdx.x;
    if (e >= E) return;
    int d = g_dst[e];
    int p = atomicAdd(&g_cursor[d], 1);
    g_colidx[p] = g_src[e];
}

// ---------------- fused LSTM layer, f32x2 edition ----------------
// 72 batch rows per CTA (8 warps x 9 rows), 256 threads.
// Thread (warp w, lane l) owns rows w*9..w*9+8 and units u0=2l, u0+1 for all
// four gates -> gates live in registers through the cell update (no gate smem).
// smem: combined weights Wc[K][256] + transposed activations inb[K][LPAD].
template<int LAYER>
__global__ void __launch_bounds__(256, 1)
lstm_kernel(const float* __restrict__ xin,
            const float* __restrict__ Wih, const float* __restrict__ Whh,
            const float* __restrict__ bih, const float* __restrict__ bhh)
{
    constexpr int D = (LAYER == 0) ? INDIM : HDIM;
    constexpr int K = D + HDIM;
    const float* src = (LAYER == 0) ? xin : g_h0seq;

    extern __shared__ float sm[];
    float* Wc  = sm;                 // K*256
    float* inb = Wc + K * GDIM;      // K*LPAD (transposed activations)

    const int tid  = threadIdx.x;
    const int lane = tid & 31;
    const int wid  = tid >> 5;
    const int wr0  = wid * 9;        // first row of this warp's 9-row group
    const int u0   = lane * 2;       // this thread's unit pair
    const int row0 = blockIdx.x * LROWS;

    // stage weights: Wc = [Wih ; Whh], layout [k][col]
    for (int idx = tid; idx < D * GDIM;    idx += 256) Wc[idx] = Wih[idx];
    for (int idx = tid; idx < HDIM * GDIM; idx += 256) Wc[D * GDIM + idx] = Whh[idx];
    // h_{-1} = 0
    for (int idx = tid; idx < HDIM * LPAD; idx += 256) inb[D * LPAD + idx] = 0.f;

    // per-thread bias (constant over t): gate g, unit lo/hi
    float bz[4][2];
#pragma unroll
    for (int g = 0; g < 4; g++) {
        bz[g][0] = bih[g * 64 + u0]     + bhh[g * 64 + u0];
        bz[g][1] = bih[g * 64 + u0 + 1] + bhh[g * 64 + u0 + 1];
    }

    float c0[9], c1[9];
#pragma unroll
    for (int r = 0; r < 9; r++) { c0[r] = 0.f; c1[r] = 0.f; }

    __syncthreads();

    for (int t = 0; t < TT; t++) {
        // stage x_t transposed: inb[k][r]
        for (int idx = tid; idx < LROWS * D; idx += 256) {
            int r = idx / D, k = idx - r * D;
            float v = (row0 + r < NN)
                ? src[((size_t)(row0 + r) * TT + t) * D + k] : 0.f;
            inb[k * LPAD + r] = v;
        }
        __syncthreads();

        // GEMM: acc[g][r] (f32x2 over units u0,u0+1) += a[r] * W[k][g*64+u0..+1]
        unsigned long long acc[4][9];
#pragma unroll
        for (int g = 0; g < 4; g++)
#pragma unroll
            for (int r = 0; r < 9; r++) acc[g][r] = 0ull;

#pragma unroll 2
        for (int k = 0; k < K; k++) {
            const float* arow = &inb[k * LPAD + wr0];
            unsigned long long ad[9];
#pragma unroll
            for (int r = 0; r < 9; r++) ad[r] = dup2(arow[r]);   // broadcast LDS
            const float* wrow = &Wc[k * GDIM + u0];
            unsigned long long w0 = *(const unsigned long long*)(wrow);
            unsigned long long w1 = *(const unsigned long long*)(wrow + 64);
            unsigned long long w2 = *(const unsigned long long*)(wrow + 128);
            unsigned long long w3 = *(const unsigned long long*)(wrow + 192);
#pragma unroll
            for (int r = 0; r < 9; r++) {
                ffma2(acc[0][r], ad[r], w0);
                ffma2(acc[1][r], ad[r], w1);
                ffma2(acc[2][r], ad[r], w2);
                ffma2(acc[3][r], ad[r], w3);
            }
        }
        __syncthreads();   // all GEMM reads of inb complete before h overwrite

        // cell update fully in registers; write h back into inb + outputs
#pragma unroll
        for (int r = 0; r < 9; r++) {
            float gi0, gi1, gf0, gf1, gc0, gc1, go0, go1;
            unpk2(acc[0][r], gi0, gi1);
            unpk2(acc[1][r], gf0, gf1);
            unpk2(acc[2][r], gc0, gc1);
            unpk2(acc[3][r], go0, go1);

            float i0 = sigm_f(gi0 + bz[0][0]), i1 = sigm_f(gi1 + bz[0][1]);
            float f0 = sigm_f(gf0 + bz[1][0]), f1 = sigm_f(gf1 + bz[1][1]);
            float gg0 = tanh_f(gc0 + bz[2][0]), gg1 = tanh_f(gc1 + bz[2][1]);
            float o0 = sigm_f(go0 + bz[3][0]), o1 = sigm_f(go1 + bz[3][1]);

            c0[r] = f0 * c0[r] + i0 * gg0;
            c1[r] = f1 * c1[r] + i1 * gg1;
            float h0 = o0 * tanh_f(c0[r]);
            float h1 = o1 * tanh_f(c1[r]);

            inb[(D + u0)     * LPAD + wr0 + r] = h0;
            inb[(D + u0 + 1) * LPAD + wr0 + r] = h1;

            int grow = row0 + wr0 + r;
            if (LAYER == 0) {
                if (grow < NN)
                    *(float2*)&g_h0seq[((size_t)grow * TT + t) * HDIM + u0] =
                        make_float2(h0, h1);
            } else if (t == TT - 1) {
                if (grow < NN)
                    *(float2*)&g_hlast[(size_t)grow * HDIM + u0] = make_float2(h0, h1);
            }
        }
        __syncthreads();   // h writes visible before next t's GEMM
    }
}

// ---------------- GAT1 feature GEMM: hlast(N,64) @ W1(64,256) ----------------
__global__ void __launch_bounds__(256) gemm1_kernel(const float* __restrict__ W1) {
    __shared__ float hs[8 * 64];
    int tid = threadIdx.x;
    int n0 = blockIdx.x * 8;
    for (int idx = tid; idx < 8 * 64; idx += 256) hs[idx] = g_hlast[(size_t)n0 * 64 + idx];
    __syncthreads();
    int j = tid;
    float acc[8];
#pragma unroll
    for (int nn = 0; nn < 8; nn++) acc[nn] = 0.f;
    for (int k = 0; k < 64; k++) {
        float w = W1[k * 256 + j];
#pragma unroll
        for (int nn = 0; nn < 8; nn++) acc[nn] += w * hs[nn * 64 + k];
    }
#pragma unroll
    for (int nn = 0; nn < 8; nn++)
        g_hfeat1[(size_t)(n0 + nn) * 256 + j] = acc[nn];
}

__global__ void attn1_kernel(const float* __restrict__ as1, const float* __restrict__ ad1) {
    int idx = blockIdx.x * blockDim.x + threadIdx.x;
    if (idx >= NN * 4) return;
    int n = idx >> 2, hd = idx & 3;
    const float* hp = g_hfeat1 + (size_t)n * 256 + hd * 64;
    float ss = 0.f, sd = 0.f;
    for (int cix = 0; cix < 64; cix++) {
        float v = hp[cix];
        ss += v * as1[hd * 64 + cix];
        sd += v * ad1[hd * 64 + cix];
    }
    g_asrc1[idx] = ss;
    g_adst1[idx] = sd;
}

__device__ __forceinline__ void online_upd(float& m, float& s, float l) {
    if (l > m) { s = s * expf(m - l) + 1.f; m = l; }
    else       { s += expf(l - m); }
}

// ---------------- GAT1 gather: warp per node, softmax over incoming edges ----------------
__global__ void __launch_bounds__(256) gather1_kernel(const float* __restrict__ b1) {
    int warp = (blockIdx.x * blockDim.x + threadIdx.x) >> 5;
    int lane = threadIdx.x & 31;
    if (warp >= NN) return;
    int d = warp;
    int base = g_rowptr[d], end = g_rowptr[d + 1];

    float4 ad = *(const float4*)(g_adst1 + 4 * d);

    // pass 1: per-lane online max/sum per head, then warp combine
    float m0 = -FLT_MAX, m1 = -FLT_MAX, m2 = -FLT_MAX, m3 = -FLT_MAX;
    float s0 = 0.f, s1 = 0.f, s2 = 0.f, s3 = 0.f;
    for (int i = base + lane; i < end; i += 32) {
        int s = g_colidx[i];
        float4 av = *(const float4*)(g_asrc1 + 4 * s);
        online_upd(m0, s0, lrelu(av.x + ad.x));
        online_upd(m1, s1, lrelu(av.y + ad.y));
        online_upd(m2, s2, lrelu(av.z + ad.z));
        online_upd(m3, s3, lrelu(av.w + ad.w));
    }
    int hd_l = lane >> 3;
    float mh = 0.f, ish = 0.f, adl = 0.f;
    {
        float M, S;
        M = warp_max(m0); S = warp_sum(s0 * expf(m0 - M));
        if (hd_l == 0) { mh = M; ish = 1.f / S; adl = ad.x; }
        M = warp_max(m1); S = warp_sum(s1 * expf(m1 - M));
        if (hd_l == 1) { mh = M; ish = 1.f / S; adl = ad.y; }
        M = warp_max(m2); S = warp_sum(s2 * expf(m2 - M));
        if (hd_l == 2) { mh = M; ish = 1.f / S; adl = ad.z; }
        M = warp_max(m3); S = warp_sum(s3 * expf(m3 - M));
        if (hd_l == 3) { mh = M; ish = 1.f / S; adl = ad.w; }
    }

    // pass 2: weighted gather; lane owns channels [lane*8, lane*8+8)
    float acc[8];
#pragma unroll
    for (int q = 0; q < 8; q++) acc[q] = 0.f;
    for (int i = base; i < end; i++) {
        int s = g_colidx[i];
        float l = lrelu(g_asrc1[s * 4 + hd_l] + adl);
        float w = expf(l - mh) * ish;
        const float4* hp = (const float4*)(g_hfeat1 + (size_t)s * 256 + lane * 8);
        float4 u = hp[0], v = hp[1];
        acc[0] += w * u.x; acc[1] += w * u.y; acc[2] += w * u.z; acc[3] += w * u.w;
        acc[4] += w * v.x; acc[5] += w * v.y; acc[6] += w * v.z; acc[7] += w * v.w;
    }
    size_t ob = (size_t)d * 256 + lane * 8;
#pragma unroll
    for (int q = 0; q < 8; q++) {
        float o = acc[q] + b1[lane * 8 + q];
        g_out1[ob + q] = o > 0.f ? o : 0.f;   // relu folded for GAT2 input
    }
}

// ---------------- GAT2 feature GEMM: relu(out1)(N,256) @ W2(256,32) ----------------
__global__ void __launch_bounds__(256) gemm2_kernel(const float* __restrict__ W2) {
    __shared__ float W2s[256 * 32];   // 32 KB
    __shared__ float ins[16 * 256];   // 16 KB
    int tid = threadIdx.x;
    int n0 = blockIdx.x * 16;
    for (int idx = tid; idx < 256 * 32; idx += 256) W2s[idx] = W2[idx];
    for (int idx = tid; idx < 16 * 256; idx += 256) ins[idx] = g_out1[(size_t)n0 * 256 + idx];
    __syncthreads();
    int cix = tid & 31;
    int ng = tid >> 5;               // 0..7
    float acc[2] = {0.f, 0.f};
    for (int k = 0; k < 256; k++) {
        float w = W2s[k * 32 + cix];
        acc[0] += w * ins[ng * 256 + k];
        acc[1] += w * ins[(ng + 8) * 256 + k];
    }
    g_hfeat2[(size_t)(n0 + ng) * 32 + cix]     = acc[0];
    g_hfeat2[(size_t)(n0 + ng + 8) * 32 + cix] = acc[1];
}

__global__ void attn2_kernel(const float* __restrict__ as2, const float* __restrict__ ad2) {
    int n = blockIdx.x * blockDim.x + threadIdx.x;
    if (n >= NN) return;
    const float* hp = g_hfeat2 + (size_t)n * 32;
    float ss = 0.f, sd = 0.f;
    for (int cix = 0; cix < 32; cix++) {
        float v = hp[cix];
        ss += v * as2[cix];
        sd += v * ad2[cix];
    }
    g_asrc2[n] = ss;
    g_adst2[n] = sd;
}

__global__ void __launch_bounds__(256) gather2_kernel(const float* __restrict__ b2,
                                                      float* __restrict__ out) {
    int warp = (blockIdx.x * blockDim.x + threadIdx.x) >> 5;
    int lane = threadIdx.x & 31;
    if (warp >= NN) return;
    int d = warp;
    int base = g_rowptr[d], end = g_rowptr[d + 1];
    float adv = g_adst2[d];

    float m = -FLT_MAX, s = 0.f;
    for (int i = base + lane; i < end; i += 32) {
        int sidx = g_colidx[i];
        online_upd(m, s, lrelu(g_asrc2[sidx] + adv));
    }
    float M = warp_max(m);
    float S = warp_sum(s * expf(m - M));
    float ish = 1.f / S;

    float acc = 0.f;
    for (int i = base; i < end; i++) {
        int sidx = g_colidx[i];
        float l = lrelu(g_asrc2[sidx] + adv);
        float w = expf(l - M) * ish;
        acc += w * g_hfeat2[(size_t)sidx * 32 + lane];
    }
    out[(size_t)d * 32 + lane] = acc + b2[lane];
}

// ---------------- launch ----------------
extern "C" void kernel_launch(void* const* d_in, const int* in_sizes, int n_in,
                              void* d_out, int out_size) {
    const float* x     = (const float*)d_in[0];
    const int*   ei    = (const int*)d_in[1];
    const float* Wih0  = (const float*)d_in[2];
    const float* Whh0  = (const float*)d_in[3];
    const float* bih0  = (const float*)d_in[4];
    const float* bhh0  = (const float*)d_in[5];
    const float* Wih1  = (const float*)d_in[6];
    const float* Whh1  = (const float*)d_in[7];
    const float* bih1  = (const float*)d_in[8];
    const float* bhh1  = (const float*)d_in[9];
    const float* W1    = (const float*)d_in[10];
    const float* as1   = (const float*)d_in[11];
    const float* ad1   = (const float*)d_in[12];
    const float* b1    = (const float*)d_in[13];
    const float* W2    = (const float*)d_in[14];
    const float* as2   = (const float*)d_in[15];
    const float* ad2   = (const float*)d_in[16];
    const float* b2    = (const float*)d_in[17];
    float* out = (float*)d_out;

    int E = in_sizes[1] / 2;
    if (E > MAXE) E = MAXE;

    const int SMEM0 = (INDIM + HDIM) * GDIM * 4 + (INDIM + HDIM) * LPAD * 4;
    const int SMEM1 = (HDIM + HDIM)  * GDIM * 4 + (HDIM + HDIM)  * LPAD * 4;
    cudaFuncSetAttribute(lstm_kernel<0>, cudaFuncAttributeMaxDynamicSharedMemorySize, SMEM0);
    cudaFuncSetAttribute(lstm_kernel<1>, cudaFuncAttributeMaxDynamicSharedMemorySize, SMEM1);

    const int LGRID = (NN + LROWS - 1) / LROWS;   // 278 -> clean 2 waves on 148 SMs

    // edge normalization (lstm0 placed early so ncu -s lands on it)
    detect_kernel<<<1, 32>>>(ei, E);
    norm_kernel<<<(E + 255) / 256, 256>>>(ei, E);
    init_counts_kernel<<<(NN + 255) / 256, 256>>>();

    lstm_kernel<0><<<LGRID, 256, SMEM0>>>(x, Wih0, Whh0, bih0, bhh0);

    count_kernel<<<(E + 255) / 256, 256>>>(E);
    scan_kernel<<<1, 1024>>>();
    selfloop_kernel<<<(NN + 255) / 256, 256>>>();
    fill_kernel<<<(E + 255) / 256, 256>>>(E);

    lstm_kernel<1><<<LGRID, 256, SMEM1>>>(x, Wih1, Whh1, bih1, bhh1);

    // GAT layer 1
    gemm1_kernel<<<NN / 8, 256>>>(W1);
    attn1_kernel<<<(NN * 4 + 255) / 256, 256>>>(as1, ad1);
    gather1_kernel<<<(NN * 32 + 255) / 256, 256>>>(b1);

    // GAT layer 2
    gemm2_kernel<<<NN / 16, 256>>>(W2);
    attn2_kernel<<<(NN + 255) / 256, 256>>>(as2, ad2);
    gather2_kernel<<<(NN * 32 + 255) / 256, 256>>>(b2, out);

    (void)n_in; (void)out_size;
}

// round 9
// speedup vs baseline: 1.8898x; 1.1220x over previous
#include <cuda_runtime.h>
#include <math.h>
#include <float.h>
#include <stdint.h>

#define NN    20000
#define TT    30
#define INDIM 32
#define HDIM  64
#define GDIM  256          // 4*H
#define MAXE  524288

#define LTHREADS 384       // 12 warps -> 3 warps/SMSP
#define RW    12           // rows per warp
#define LROWS 144          // rows per LSTM CTA (12 warps x 12 rows); grid=139 -> 1 wave
#define LPAD  149          // row pitch in inb (odd mod 32 -> conflict-free staging)

// ---------------- scratch (device globals; no allocation allowed) ----------------
static __device__ float g_h0seq[(size_t)NN * TT * HDIM];   // layer0 hidden sequence
static __device__ float g_hlast[NN * HDIM];
static __device__ float g_hfeat1[NN * GDIM];
static __device__ float g_out1[NN * GDIM];                 // relu(gat1 + b1)
static __device__ float g_hfeat2[NN * 32];
static __device__ float g_asrc1[NN * 4], g_adst1[NN * 4];
static __device__ float g_asrc2[NN], g_adst2[NN];
static __device__ int   g_src[MAXE], g_dst[MAXE];
static __device__ int   g_colidx[MAXE + NN];
static __device__ int   g_rowptr[NN + 1];
static __device__ int   g_cursor[NN];
static __device__ int   g_counts[NN];
static __device__ int   g_is64;

// ---------------- helpers ----------------
__device__ __forceinline__ float lrelu(float x) { return x > 0.f ? x : 0.2f * x; }

// fast-but-accurate-enough activations (err ~1e-6 rel; budget is 1e-3)
__device__ __forceinline__ float sigm_f(float x)  { return __fdividef(1.f, 1.f + __expf(-x)); }
__device__ __forceinline__ float tanh_f(float x)  { return __fdividef(2.f, 1.f + __expf(-2.f * x)) - 1.f; }

__device__ __forceinline__ float warp_max(float v) {
#pragma unroll
    for (int o = 16; o > 0; o >>= 1) v = fmaxf(v, __shfl_xor_sync(0xffffffffu, v, o));
    return v;
}
__device__ __forceinline__ float warp_sum(float v) {
#pragma unroll
    for (int o = 16; o > 0; o >>= 1) v += __shfl_xor_sync(0xffffffffu, v, o);
    return v;
}

// ---- f32x2 packed-math primitives (SASS FFMA2 is PTX-only) ----
__device__ __forceinline__ void ffma2(unsigned long long& d, unsigned long long a, unsigned long long b) {
    asm("fma.rn.f32x2 %0, %1, %2, %3;" : "=l"(d) : "l"(a), "l"(b), "l"(d));
}
__device__ __forceinline__ unsigned long long dup2(float v) {
    unsigned long long r;
    asm("mov.b64 %0, {%1, %1};" : "=l"(r) : "f"(v));
    return r;
}
__device__ __forceinline__ void unpk2(unsigned long long v, float& lo, float& hi) {
    asm("mov.b64 {%0, %1}, %2;" : "=f"(lo), "=f"(hi) : "l"(v));
}

// ---------------- edge dtype handling ----------------
__global__ void detect_kernel(const int* __restrict__ w, int E) {
    if (blockIdx.x == 0 && threadIdx.x == 0) {
        int n = E < 64 ? E : 64;
        int f = 1;
        for (int i = 0; i < n; i++)
            if (w[2 * i + 1] != 0) f = 0;   // int64 node ids < 2^31 => high words all 0
        g_is64 = f;
    }
}

__global__ void norm_kernel(const int* __restrict__ w, int E) {
    int e = blockIdx.x * blockDim.x + threadIdx.x;
    if (e >= E) return;
    if (g_is64) {
        g_src[e] = w[2 * e];
        g_dst[e] = w[2 * (E + e)];
    } else {
        g_src[e] = w[e];
        g_dst[e] = w[E + e];
    }
}

// ---------------- CSR build (dst-grouped, self-loop first) ----------------
__global__ void init_counts_kernel() {
    int i = blockIdx.x * blockDim.x + threadIdx.x;
    if (i < NN) g_counts[i] = 1;           // self loop
}
__global__ void count_kernel(int E) {
    int e = blockIdx.x * blockDim.x + threadIdx.x;
    if (e < E) atomicAdd(&g_counts[g_dst[e]], 1);
}
__global__ void scan_kernel() {
    __shared__ int part[1024];
    const int CH = 20;                     // 1024*20 >= 20000
    int tid = threadIdx.x;
    int b = tid * CH;
    int s = 0;
    for (int i = 0; i < CH; i++)
        if (b + i < NN) s += g_counts[b + i];
    part[tid] = s;
    __syncthreads();
    for (int off = 1; off < 1024; off <<= 1) {
        int v = (tid >= off) ? part[tid - off] : 0;
        __syncthreads();
        part[tid] += v;
        __syncthreads();
    }
    int run = part[tid] - s;               // exclusive prefix
    for (int i = 0; i < CH; i++)
        if (b + i < NN) { g_rowptr[b + i] = run; run += g_counts[b + i]; }
    if (tid == 1023) g_rowptr[NN] = part[1023];
}
__global__ void selfloop_kernel() {
    int d = blockIdx.x * blockDim.x + threadIdx.x;
    if (d >= NN) return;
    int p = g_rowptr[d];
    g_colidx[p] = d;
    g_cursor[d] = p + 1;
}
__global__ void fill_kernel(int E) {
    int e = blockIdx.x * blockDim.x + threadIdx.x;
    if (e >= E) return;
    int d = g_dst[e];
    int p = atomicAdd(&g_cursor[d], 1);
    g_colidx[p] = g_src[e];
}

// ---------------- fused LSTM layer, f32x2, 3 warps/SMSP, single wave ----------------
// 144 batch rows per CTA (12 warps x 12 rows), 384 threads.
// Thread (warp w, lane l) owns rows w*12..w*12+11 and units u0=2l, u0+1 for all
// four gates -> gates live in registers through the cell update (no gate smem).
// smem: combined weights Wc[K][256] + transposed activations inb[K][LPAD].
template<int LAYER>
__global__ void __launch_bounds__(LTHREADS, 1)
lstm_kernel(const float* __restrict__ xin,
            const float* __restrict__ Wih, const float* __restrict__ Whh,
            const float* __restrict__ bih, const float* __restrict__ bhh)
{
    constexpr int D = (LAYER == 0) ? INDIM : HDIM;
    constexpr int K = D + HDIM;
    const float* src = (LAYER == 0) ? xin : g_h0seq;

    extern __shared__ float sm[];
    float* Wc  = sm;                 // K*256
    float* inb = Wc + K * GDIM;      // K*LPAD (transposed activations)

    const int tid  = threadIdx.x;
    const int lane = tid & 31;
    const int wid  = tid >> 5;
    const int wr0  = wid * RW;       // first row of this warp's 12-row group
    const int u0   = lane * 2;       // this thread's unit pair
    const int row0 = blockIdx.x * LROWS;

    // stage weights: Wc = [Wih ; Whh], layout [k][col]
    for (int idx = tid; idx < D * GDIM;    idx += LTHREADS) Wc[idx] = Wih[idx];
    for (int idx = tid; idx < HDIM * GDIM; idx += LTHREADS) Wc[D * GDIM + idx] = Whh[idx];
    // h_{-1} = 0
    for (int idx = tid; idx < HDIM * LPAD; idx += LTHREADS) inb[D * LPAD + idx] = 0.f;

    // per-thread bias (constant over t): gate g, unit lo/hi
    float bz[4][2];
#pragma unroll
    for (int g = 0; g < 4; g++) {
        bz[g][0] = bih[g * 64 + u0]     + bhh[g * 64 + u0];
        bz[g][1] = bih[g * 64 + u0 + 1] + bhh[g * 64 + u0 + 1];
    }

    float c0[RW], c1[RW];
#pragma unroll
    for (int r = 0; r < RW; r++) { c0[r] = 0.f; c1[r] = 0.f; }

    __syncthreads();

    for (int t = 0; t < TT; t++) {
        // stage x_t transposed: inb[k][r]
        for (int idx = tid; idx < LROWS * D; idx += LTHREADS) {
            int r = idx / D, k = idx - r * D;
            float v = (row0 + r < NN)
                ? src[((size_t)(row0 + r) * TT + t) * D + k] : 0.f;
            inb[k * LPAD + r] = v;
        }
        __syncthreads();

        // GEMM: acc[g][r] (f32x2 over units u0,u0+1) += a[r] * W[k][g*64+u0..+1]
        unsigned long long acc[4][RW];
#pragma unroll
        for (int g = 0; g < 4; g++)
#pragma unroll
            for (int r = 0; r < RW; r++) acc[g][r] = 0ull;

#pragma unroll 2
        for (int k = 0; k < K; k++) {
            const float* wrow = &Wc[k * GDIM + u0];
            unsigned long long w0 = *(const unsigned long long*)(wrow);
            unsigned long long w1 = *(const unsigned long long*)(wrow + 64);
            unsigned long long w2 = *(const unsigned long long*)(wrow + 128);
            unsigned long long w3 = *(const unsigned long long*)(wrow + 192);
            const float* arow = &inb[k * LPAD + wr0];
#pragma unroll
            for (int r = 0; r < RW; r++) {
                unsigned long long ad = dup2(arow[r]);   // broadcast LDS + pack
                ffma2(acc[0][r], ad, w0);
                ffma2(acc[1][r], ad, w1);
                ffma2(acc[2][r], ad, w2);
                ffma2(acc[3][r], ad, w3);
            }
        }
        __syncthreads();   // all GEMM reads of inb complete before h overwrite

        // cell update fully in registers; write h back into inb + outputs
#pragma unroll
        for (int r = 0; r < RW; r++) {
            float gi0, gi1, gf0, gf1, gc0, gc1, go0, go1;
            unpk2(acc[0][r], gi0, gi1);
            unpk2(acc[1][r], gf0, gf1);
            unpk2(acc[2][r], gc0, gc1);
            unpk2(acc[3][r], go0, go1);

            float i0 = sigm_f(gi0 + bz[0][0]), i1 = sigm_f(gi1 + bz[0][1]);
            float f0 = sigm_f(gf0 + bz[1][0]), f1 = sigm_f(gf1 + bz[1][1]);
            float gg0 = tanh_f(gc0 + bz[2][0]), gg1 = tanh_f(gc1 + bz[2][1]);
            float o0 = sigm_f(go0 + bz[3][0]), o1 = sigm_f(go1 + bz[3][1]);

            c0[r] = f0 * c0[r] + i0 * gg0;
            c1[r] = f1 * c1[r] + i1 * gg1;
            float h0 = o0 * tanh_f(c0[r]);
            float h1 = o1 * tanh_f(c1[r]);

            inb[(D + u0)     * LPAD + wr0 + r] = h0;
            inb[(D + u0 + 1) * LPAD + wr0 + r] = h1;

            int grow = row0 + wr0 + r;
            if (LAYER == 0) {
                if (grow < NN)
                    *(float2*)&g_h0seq[((size_t)grow * TT + t) * HDIM + u0] =
                        make_float2(h0, h1);
            } else if (t == TT - 1) {
                if (grow < NN)
                    *(float2*)&g_hlast[(size_t)grow * HDIM + u0] = make_float2(h0, h1);
            }
        }
        __syncthreads();   // h writes visible before next t's GEMM
    }
}

// ---------------- GAT1 feature GEMM: hlast(N,64) @ W1(64,256) ----------------
__global__ void __launch_bounds__(256) gemm1_kernel(const float* __restrict__ W1) {
    __shared__ float hs[8 * 64];
    int tid = threadIdx.x;
    int n0 = blockIdx.x * 8;
    for (int idx = tid; idx < 8 * 64; idx += 256) hs[idx] = g_hlast[(size_t)n0 * 64 + idx];
    __syncthreads();
    int j = tid;
    float acc[8];
#pragma unroll
    for (int nn = 0; nn < 8; nn++) acc[nn] = 0.f;
    for (int k = 0; k < 64; k++) {
        float w = W1[k * 256 + j];
#pragma unroll
        for (int nn = 0; nn < 8; nn++) acc[nn] += w * hs[nn * 64 + k];
    }
#pragma unroll
    for (int nn = 0; nn < 8; nn++)
        g_hfeat1[(size_t)(n0 + nn) * 256 + j] = acc[nn];
}

__global__ void attn1_kernel(const float* __restrict__ as1, const float* __restrict__ ad1) {
    int idx = blockIdx.x * blockDim.x + threadIdx.x;
    if (idx >= NN * 4) return;
    int n = idx >> 2, hd = idx & 3;
    const float* hp = g_hfeat1 + (size_t)n * 256 + hd * 64;
    float ss = 0.f, sd = 0.f;
    for (int cix = 0; cix < 64; cix++) {
        float v = hp[cix];
        ss += v * as1[hd * 64 + cix];
        sd += v * ad1[hd * 64 + cix];
    }
    g_asrc1[idx] = ss;
    g_adst1[idx] = sd;
}

__device__ __forceinline__ void online_upd(float& m, float& s, float l) {
    if (l > m) { s = s * expf(m - l) + 1.f; m = l; }
    else       { s += expf(l - m); }
}

// ---------------- GAT1 gather: warp per node, softmax over incoming edges ----------------
__global__ void __launch_bounds__(256) gather1_kernel(const float* __restrict__ b1) {
    int warp = (blockIdx.x * blockDim.x + threadIdx.x) >> 5;
    int lane = threadIdx.x & 31;
    if (warp >= NN) return;
    int d = warp;
    int base = g_rowptr[d], end = g_rowptr[d + 1];

    float4 ad = *(const float4*)(g_adst1 + 4 * d);

    // pass 1: per-lane online max/sum per head, then warp combine
    float m0 = -FLT_MAX, m1 = -FLT_MAX, m2 = -FLT_MAX, m3 = -FLT_MAX;
    float s0 = 0.f, s1 = 0.f, s2 = 0.f, s3 = 0.f;
    for (int i = base + lane; i < end; i += 32) {
        int s = g_colidx[i];
        float4 av = *(const float4*)(g_asrc1 + 4 * s);
        online_upd(m0, s0, lrelu(av.x + ad.x));
        online_upd(m1, s1, lrelu(av.y + ad.y));
        online_upd(m2, s2, lrelu(av.z + ad.z));
        online_upd(m3, s3, lrelu(av.w + ad.w));
    }
    int hd_l = lane >> 3;
    float mh = 0.f, ish = 0.f, adl = 0.f;
    {
        float M, S;
        M = warp_max(m0); S = warp_sum(s0 * expf(m0 - M));
        if (hd_l == 0) { mh = M; ish = 1.f / S; adl = ad.x; }
        M = warp_max(m1); S = warp_sum(s1 * expf(m1 - M));
        if (hd_l == 1) { mh = M; ish = 1.f / S; adl = ad.y; }
        M = warp_max(m2); S = warp_sum(s2 * expf(m2 - M));
        if (hd_l == 2) { mh = M; ish = 1.f / S; adl = ad.z; }
        M = warp_max(m3); S = warp_sum(s3 * expf(m3 - M));
        if (hd_l == 3) { mh = M; ish = 1.f / S; adl = ad.w; }
    }

    // pass 2: weighted gather; lane owns channels [lane*8, lane*8+8)
    float acc[8];
#pragma unroll
    for (int q = 0; q < 8; q++) acc[q] = 0.f;
    for (int i = base; i < end; i++) {
        int s = g_colidx[i];
        float l = lrelu(g_asrc1[s * 4 + hd_l] + adl);
        float w = expf(l - mh) * ish;
        const float4* hp = (const float4*)(g_hfeat1 + (size_t)s * 256 + lane * 8);
        float4 u = hp[0], v = hp[1];
        acc[0] += w * u.x; acc[1] += w * u.y; acc[2] += w * u.z; acc[3] += w * u.w;
        acc[4] += w * v.x; acc[5] += w * v.y; acc[6] += w * v.z; acc[7] += w * v.w;
    }
    size_t ob = (size_t)d * 256 + lane * 8;
#pragma unroll
    for (int q = 0; q < 8; q++) {
        float o = acc[q] + b1[lane * 8 + q];
        g_out1[ob + q] = o > 0.f ? o : 0.f;   // relu folded for GAT2 input
    }
}

// ---------------- GAT2 feature GEMM: relu(out1)(N,256) @ W2(256,32) ----------------
__global__ void __launch_bounds__(256) gemm2_kernel(const float* __restrict__ W2) {
    __shared__ float W2s[256 * 32];   // 32 KB
    __shared__ float ins[16 * 256];   // 16 KB
    int tid = threadIdx.x;
    int n0 = blockIdx.x * 16;
    for (int idx = tid; idx < 256 * 32; idx += 256) W2s[idx] = W2[idx];
    for (int idx = tid; idx < 16 * 256; idx += 256) ins[idx] = g_out1[(size_t)n0 * 256 + idx];
    __syncthreads();
    int cix = tid & 31;
    int ng = tid >> 5;               // 0..7
    float acc[2] = {0.f, 0.f};
    for (int k = 0; k < 256; k++) {
        float w = W2s[k * 32 + cix];
        acc[0] += w * ins[ng * 256 + k];
        acc[1] += w * ins[(ng + 8) * 256 + k];
    }
    g_hfeat2[(size_t)(n0 + ng) * 32 + cix]     = acc[0];
    g_hfeat2[(size_t)(n0 + ng + 8) * 32 + cix] = acc[1];
}

__global__ void attn2_kernel(const float* __restrict__ as2, const float* __restrict__ ad2) {
    int n = blockIdx.x * blockDim.x + threadIdx.x;
    if (n >= NN) return;
    const float* hp = g_hfeat2 + (size_t)n * 32;
    float ss = 0.f, sd = 0.f;
    for (int cix = 0; cix < 32; cix++) {
        float v = hp[cix];
        ss += v * as2[cix];
        sd += v * ad2[cix];
    }
    g_asrc2[n] = ss;
    g_adst2[n] = sd;
}

__global__ void __launch_bounds__(256) gather2_kernel(const float* __restrict__ b2,
                                                      float* __restrict__ out) {
    int warp = (blockIdx.x * blockDim.x + threadIdx.x) >> 5;
    int lane = threadIdx.x & 31;
    if (warp >= NN) return;
    int d = warp;
    int base = g_rowptr[d], end = g_rowptr[d + 1];
    float adv = g_adst2[d];

    float m = -FLT_MAX, s = 0.f;
    for (int i = base + lane; i < end; i += 32) {
        int sidx = g_colidx[i];
        online_upd(m, s, lrelu(g_asrc2[sidx] + adv));
    }
    float M = warp_max(m);
    float S = warp_sum(s * expf(m - M));
    float ish = 1.f / S;

    float acc = 0.f;
    for (int i = base; i < end; i++) {
        int sidx = g_colidx[i];
        float l = lrelu(g_asrc2[sidx] + adv);
        float w = expf(l - M) * ish;
        acc += w * g_hfeat2[(size_t)sidx * 32 + lane];
    }
    out[(size_t)d * 32 + lane] = acc + b2[lane];
}

// ---------------- launch ----------------
extern "C" void kernel_launch(void* const* d_in, const int* in_sizes, int n_in,
                              void* d_out, int out_size) {
    const float* x     = (const float*)d_in[0];
    const int*   ei    = (const int*)d_in[1];
    const float* Wih0  = (const float*)d_in[2];
    const float* Whh0  = (const float*)d_in[3];
    const float* bih0  = (const float*)d_in[4];
    const float* bhh0  = (const float*)d_in[5];
    const float* Wih1  = (const float*)d_in[6];
    const float* Whh1  = (const float*)d_in[7];
    const float* bih1  = (const float*)d_in[8];
    const float* bhh1  = (const float*)d_in[9];
    const float* W1    = (const float*)d_in[10];
    const float* as1   = (const float*)d_in[11];
    const float* ad1   = (const float*)d_in[12];
    const float* b1    = (const float*)d_in[13];
    const float* W2    = (const float*)d_in[14];
    const float* as2   = (const float*)d_in[15];
    const float* ad2   = (const float*)d_in[16];
    const float* b2    = (const float*)d_in[17];
    float* out = (float*)d_out;

    int E = in_sizes[1] / 2;
    if (E > MAXE) E = MAXE;

    const int SMEM0 = (INDIM + HDIM) * GDIM * 4 + (INDIM + HDIM) * LPAD * 4;
    const int SMEM1 = (HDIM + HDIM)  * GDIM * 4 + (HDIM + HDIM)  * LPAD * 4;
    cudaFuncSetAttribute(lstm_kernel<0>, cudaFuncAttributeMaxDynamicSharedMemorySize, SMEM0);
    cudaFuncSetAttribute(lstm_kernel<1>, cudaFuncAttributeMaxDynamicSharedMemorySize, SMEM1);

    const int LGRID = (NN + LROWS - 1) / LROWS;   // 139 -> single wave on 148 SMs

    // edge normalization (lstm0 placed early so ncu -s lands on it)
    detect_kernel<<<1, 32>>>(ei, E);
    norm_kernel<<<(E + 255) / 256, 256>>>(ei, E);
    init_counts_kernel<<<(NN + 255) / 256, 256>>>();

    lstm_kernel<0><<<LGRID, LTHREADS, SMEM0>>>(x, Wih0, Whh0, bih0, bhh0);

    count_kernel<<<(E + 255) / 256, 256>>>(E);
    scan_kernel<<<1, 1024>>>();
    selfloop_kernel<<<(NN + 255) / 256, 256>>>();
    fill_kernel<<<(E + 255) / 256, 256>>>(E);

    lstm_kernel<1><<<LGRID, LTHREADS, SMEM1>>>(x, Wih1, Whh1, bih1, bhh1);

    // GAT layer 1
    gemm1_kernel<<<NN / 8, 256>>>(W1);
    attn1_kernel<<<(NN * 4 + 255) / 256, 256>>>(as1, ad1);
    gather1_kernel<<<(NN * 32 + 255) / 256, 256>>>(b1);

    // GAT layer 2
    gemm2_kernel<<<NN / 16, 256>>>(W2);
    attn2_kernel<<<(NN + 255) / 256, 256>>>(as2, ad2);
    gather2_kernel<<<(NN * 32 + 255) / 256, 256>>>(b2, out);

    (void)n_in; (void)out_size;
}

// round 13
// speedup vs baseline: 1.9145x; 1.0130x over previous
#include <cuda_runtime.h>
#include <math.h>
#include <float.h>
#include <stdint.h>

#define NN    20000
#define TT    30
#define INDIM 32
#define HDIM  64
#define GDIM  256          // 4*H
#define MAXE  524288

#define LTHREADS 384       // 12 warps -> 3 warps/SMSP
#define RW    12           // rows per warp
#define LROWS 144          // rows per LSTM CTA (12 warps x 12 rows); grid=139 -> 1 wave

// ---------------- scratch (device globals; no allocation allowed) ----------------
static __device__ float g_h0seq[(size_t)NN * TT * HDIM];   // layer0 hidden sequence
static __device__ float g_hlast[NN * HDIM];
static __device__ float g_hfeat1[NN * GDIM];
static __device__ float g_out1[NN * GDIM];                 // relu(gat1 + b1)
static __device__ float g_hfeat2[NN * 32];
static __device__ float g_asrc1[NN * 4], g_adst1[NN * 4];
static __device__ float g_asrc2[NN], g_adst2[NN];
static __device__ int   g_src[MAXE], g_dst[MAXE];
static __device__ int   g_colidx[MAXE + NN];
static __device__ int   g_rowptr[NN + 1];
static __device__ int   g_cursor[NN];
static __device__ int   g_counts[NN];
static __device__ int   g_is64;

// ---------------- helpers ----------------
__device__ __forceinline__ float lrelu(float x) { return x > 0.f ? x : 0.2f * x; }

// fast-but-accurate-enough activations (err ~1e-6 rel; budget is 1e-3)
__device__ __forceinline__ float sigm_f(float x)  { return __fdividef(1.f, 1.f + __expf(-x)); }
__device__ __forceinline__ float tanh_f(float x)  { return __fdividef(2.f, 1.f + __expf(-2.f * x)) - 1.f; }

__device__ __forceinline__ float warp_max(float v) {
#pragma unroll
    for (int o = 16; o > 0; o >>= 1) v = fmaxf(v, __shfl_xor_sync(0xffffffffu, v, o));
    return v;
}
__device__ __forceinline__ float warp_sum(float v) {
#pragma unroll
    for (int o = 16; o > 0; o >>= 1) v += __shfl_xor_sync(0xffffffffu, v, o);
    return v;
}

// ---- f32x2 packed-math primitives (SASS FFMA2 is PTX-only) ----
__device__ __forceinline__ void ffma2(unsigned long long& d, unsigned long long a, unsigned long long b) {
    asm("fma.rn.f32x2 %0, %1, %2, %3;" : "=l"(d) : "l"(a), "l"(b), "l"(d));
}
__device__ __forceinline__ unsigned long long dup2(float v) {
    unsigned long long r;
    asm("mov.b64 %0, {%1, %1};" : "=l"(r) : "f"(v));
    return r;
}
__device__ __forceinline__ void unpk2(unsigned long long v, float& lo, float& hi) {
    asm("mov.b64 {%0, %1}, %2;" : "=f"(lo), "=f"(hi) : "l"(v));
}

// ---------------- edge dtype handling ----------------
__global__ void detect_kernel(const int* __restrict__ w, int E) {
    if (blockIdx.x == 0 && threadIdx.x == 0) {
        int n = E < 64 ? E : 64;
        int f = 1;
        for (int i = 0; i < n; i++)
            if (w[2 * i + 1] != 0) f = 0;   // int64 node ids < 2^31 => high words all 0
        g_is64 = f;
    }
}

__global__ void norm_kernel(const int* __restrict__ w, int E) {
    int e = blockIdx.x * blockDim.x + threadIdx.x;
    if (e >= E) return;
    if (g_is64) {
        g_src[e] = w[2 * e];
        g_dst[e] = w[2 * (E + e)];
    } else {
        g_src[e] = w[e];
        g_dst[e] = w[E + e];
    }
}

// ---------------- CSR build (dst-grouped, self-loop first) ----------------
__global__ void init_counts_kernel() {
    int i = blockIdx.x * blockDim.x + threadIdx.x;
    if (i < NN) g_counts[i] = 1;           // self loop
}
__global__ void count_kernel(int E) {
    int e = blockIdx.x * blockDim.x + threadIdx.x;
    if (e < E) atomicAdd(&g_counts[g_dst[e]], 1);
}
__global__ void scan_kernel() {
    __shared__ int part[1024];
    const int CH = 20;                     // 1024*20 >= 20000
    int tid = threadIdx.x;
    int b = tid * CH;
    int s = 0;
    for (int i = 0; i < CH; i++)
        if (b + i < NN) s += g_counts[b + i];
    part[tid] = s;
    __syncthreads();
    for (int off = 1; off < 1024; off <<= 1) {
        int v = (tid >= off) ? part[tid - off] : 0;
        __syncthreads();
        part[tid] += v;
        __syncthreads();
    }
    int run = part[tid] - s;               // exclusive prefix
    for (int i = 0; i < CH; i++)
        if (b + i < NN) { g_rowptr[b + i] = run; run += g_counts[b + i]; }
    if (tid == 1023) g_rowptr[NN] = part[1023];
}
__global__ void selfloop_kernel() {
    int d = blockIdx.x * blockDim.x + threadIdx.x;
    if (d >= NN) return;
    int p = g_rowptr[d];
    g_colidx[p] = d;
    g_cursor[d] = p + 1;
}
__global__ void fill_kernel(int E) {
    int e = blockIdx.x * blockDim.x + threadIdx.x;
    if (e >= E) return;
    int d = g_dst[e];
    int p = atomicAdd(&g_cursor[d], 1);
    g_colidx[p] = g_src[e];
}

// ---------------- fused LSTM layer: warp-independent, zero CTA barriers in t-loop ----
// 144 rows per CTA (12 warps x 12 rows), 384 threads. Weights CTA-shared in smem.
// inb is ROW-MAJOR [row][P]: cols [0,D) = x_t, cols [D,D+64) = h_{t-1}.
// Warp w owns rows w*RW..w*RW+RW-1 exclusively (stage/GEMM/cell all private),
// so phases are separated by __syncwarp() only -> warps drift and overlap
// MUFU/staging with other warps' FFMA2.
// Thread (lane l) owns unit pair u0=2l,u0+1 for all 4 gates of its 12 rows.
template<int LAYER>
__global__ void __launch_bounds__(LTHREADS, 1)
lstm_kernel(const float* __restrict__ xin,
            const float* __restrict__ Wih, const float* __restrict__ Whh,
            const float* __restrict__ bih, const float* __restrict__ bhh)
{
    constexpr int D = (LAYER == 0) ? INDIM : HDIM;
    constexpr int K = D + HDIM;
    constexpr int P = K + 4;         // row pitch (mult of 4 -> LDS.128-aligned)
    const float* src = (LAYER == 0) ? xin : g_h0seq;

    extern __shared__ float sm[];
    float* Wc  = sm;                 // K*256
    float* inb = Wc + K * GDIM;      // LROWS * P, row-major

    const int tid  = threadIdx.x;
    const int lane = tid & 31;
    const int wid  = tid >> 5;
    const int wr0  = wid * RW;
    const int u0   = lane * 2;
    const int row0 = blockIdx.x * LROWS;

    // stage weights: Wc = [Wih ; Whh], layout [k][col] (whole CTA)
    for (int idx = tid; idx < D * GDIM;    idx += LTHREADS) Wc[idx] = Wih[idx];
    for (int idx = tid; idx < HDIM * GDIM; idx += LTHREADS) Wc[D * GDIM + idx] = Whh[idx];

    // zero own rows' h region
#pragma unroll
    for (int r = 0; r < RW; r++)
        for (int q = lane; q < HDIM; q += 32)
            inb[(wr0 + r) * P + D + q] = 0.f;

    // per-thread bias (constant over t): gate g, unit lo/hi
    float bz[4][2];
#pragma unroll
    for (int g = 0; g < 4; g++) {
        bz[g][0] = bih[g * 64 + u0]     + bhh[g * 64 + u0];
        bz[g][1] = bih[g * 64 + u0 + 1] + bhh[g * 64 + u0 + 1];
    }

    float c0[RW], c1[RW];
#pragma unroll
    for (int r = 0; r < RW; r++) { c0[r] = 0.f; c1[r] = 0.f; }

    __syncthreads();    // weights + h-zero visible

    for (int t = 0; t < TT; t++) {
        // stage x_t for OWN rows only (row-major, straight float4 copy)
#pragma unroll
        for (int r = 0; r < RW; r++) {
            int grow = row0 + wr0 + r;
            float4* drow = (float4*)&inb[(wr0 + r) * P];
            if (grow < NN) {
                const float4* xrow = (const float4*)&src[((size_t)grow * TT + t) * D];
                for (int q = lane; q < D / 4; q += 32) drow[q] = xrow[q];
            } else {
                for (int q = lane; q < D / 4; q += 32) drow[q] = make_float4(0.f, 0.f, 0.f, 0.f);
            }
        }
        __syncwarp();    // x (and prev-t h) visible warp-wide before GEMM

        // GEMM: acc[g][r] (f32x2 over units u0,u0+1) += a[row][k] * W[k][g*64+u0..+1]
        unsigned long long acc[4][RW];
#pragma unroll
        for (int g = 0; g < 4; g++)
#pragma unroll
            for (int r = 0; r < RW; r++) acc[g][r] = 0ull;

        for (int k4 = 0; k4 < K; k4 += 4) {
            // weights for 4 k's x 4 gates
            unsigned long long w[4][4];
#pragma unroll
            for (int kk = 0; kk < 4; kk++) {
                const float* wrow = &Wc[(k4 + kk) * GDIM + u0];
                w[kk][0] = *(const unsigned long long*)(wrow);
                w[kk][1] = *(const unsigned long long*)(wrow + 64);
                w[kk][2] = *(const unsigned long long*)(wrow + 128);
                w[kk][3] = *(const unsigned long long*)(wrow + 192);
            }
#pragma unroll
            for (int r = 0; r < RW; r++) {
                float4 a4 = *(const float4*)&inb[(wr0 + r) * P + k4];  // broadcast LDS.128
                unsigned long long a0 = dup2(a4.x), a1 = dup2(a4.y);
                unsigned long long a2 = dup2(a4.z), a3 = dup2(a4.w);
#pragma unroll
                for (int g = 0; g < 4; g++) {
                    ffma2(acc[g][r], a0, w[0][g]);
                    ffma2(acc[g][r], a1, w[1][g]);
                    ffma2(acc[g][r], a2, w[2][g]);
                    ffma2(acc[g][r], a3, w[3][g]);
                }
            }
        }

        // cell update fully in registers; write h into own rows + outputs
#pragma unroll
        for (int r = 0; r < RW; r++) {
            float gi0, gi1, gf0, gf1, gc0, gc1, go0, go1;
            unpk2(acc[0][r], gi0, gi1);
            unpk2(acc[1][r], gf0, gf1);
            unpk2(acc[2][r], gc0, gc1);
            unpk2(acc[3][r], go0, go1);

            float i0 = sigm_f(gi0 + bz[0][0]), i1 = sigm_f(gi1 + bz[0][1]);
            float f0 = sigm_f(gf0 + bz[1][0]), f1 = sigm_f(gf1 + bz[1][1]);
            float gg0 = tanh_f(gc0 + bz[2][0]), gg1 = tanh_f(gc1 + bz[2][1]);
            float o0 = sigm_f(go0 + bz[3][0]), o1 = sigm_f(go1 + bz[3][1]);

            c0[r] = f0 * c0[r] + i0 * gg0;
            c1[r] = f1 * c1[r] + i1 * gg1;
            float h0 = o0 * tanh_f(c0[r]);
            float h1 = o1 * tanh_f(c1[r]);

            *(float2*)&inb[(wr0 + r) * P + D + u0] = make_float2(h0, h1);

            int grow = row0 + wr0 + r;
            if (LAYER == 0) {
                if (grow < NN)
                    *(float2*)&g_h0seq[((size_t)grow * TT + t) * HDIM + u0] =
                        make_float2(h0, h1);
            } else if (t == TT - 1) {
                if (grow < NN)
                    *(float2*)&g_hlast[(size_t)grow * HDIM + u0] = make_float2(h0, h1);
            }
        }
        // h writes become visible at next iteration's __syncwarp()
    }
}

// ---------------- GAT1 feature GEMM: hlast(N,64) @ W1(64,256) ----------------
__global__ void __launch_bounds__(256) gemm1_kernel(const float* __restrict__ W1) {
    __shared__ float hs[8 * 64];
    int tid = threadIdx.x;
    int n0 = blockIdx.x * 8;
    for (int idx = tid; idx < 8 * 64; idx += 256) hs[idx] = g_hlast[(size_t)n0 * 64 + idx];
    __syncthreads();
    int j = tid;
    float acc[8];
#pragma unroll
    for (int nn = 0; nn < 8; nn++) acc[nn] = 0.f;
    for (int k = 0; k < 64; k++) {
        float w = W1[k * 256 + j];
#pragma unroll
        for (int nn = 0; nn < 8; nn++) acc[nn] += w * hs[nn * 64 + k];
    }
#pragma unroll
    for (int nn = 0; nn < 8; nn++)
        g_hfeat1[(size_t)(n0 + nn) * 256 + j] = acc[nn];
}

__global__ void attn1_kernel(const float* __restrict__ as1, const float* __restrict__ ad1) {
    int idx = blockIdx.x * blockDim.x + threadIdx.x;
    if (idx >= NN * 4) return;
    int n = idx >> 2, hd = idx & 3;
    const float* hp = g_hfeat1 + (size_t)n * 256 + hd * 64;
    float ss = 0.f, sd = 0.f;
    for (int cix = 0; cix < 64; cix++) {
        float v = hp[cix];
        ss += v * as1[hd * 64 + cix];
        sd += v * ad1[hd * 64 + cix];
    }
    g_asrc1[idx] = ss;
    g_adst1[idx] = sd;
}

__device__ __forceinline__ void online_upd(float& m, float& s, float l) {
    if (l > m) { s = s * expf(m - l) + 1.f; m = l; }
    else       { s += expf(l - m); }
}

// ---------------- GAT1 gather: warp per node, softmax over incoming edges ----------------
__global__ void __launch_bounds__(256) gather1_kernel(const float* __restrict__ b1) {
    int warp = (blockIdx.x * blockDim.x + threadIdx.x) >> 5;
    int lane = threadIdx.x & 31;
    if (warp >= NN) return;
    int d = warp;
    int base = g_rowptr[d], end = g_rowptr[d + 1];

    float4 ad = *(const float4*)(g_adst1 + 4 * d);

    // pass 1: per-lane online max/sum per head, then warp combine
    float m0 = -FLT_MAX, m1 = -FLT_MAX, m2 = -FLT_MAX, m3 = -FLT_MAX;
    float s0 = 0.f, s1 = 0.f, s2 = 0.f, s3 = 0.f;
    for (int i = base + lane; i < end; i += 32) {
        int s = g_colidx[i];
        float4 av = *(const float4*)(g_asrc1 + 4 * s);
        online_upd(m0, s0, lrelu(av.x + ad.x));
        online_upd(m1, s1, lrelu(av.y + ad.y));
        online_upd(m2, s2, lrelu(av.z + ad.z));
        online_upd(m3, s3, lrelu(av.w + ad.w));
    }
    int hd_l = lane >> 3;
    float mh = 0.f, ish = 0.f, adl = 0.f;
    {
        float M, S;
        M = warp_max(m0); S = warp_sum(s0 * expf(m0 - M));
        if (hd_l == 0) { mh = M; ish = 1.f / S; adl = ad.x; }
        M = warp_max(m1); S = warp_sum(s1 * expf(m1 - M));
        if (hd_l == 1) { mh = M; ish = 1.f / S; adl = ad.y; }
        M = warp_max(m2); S = warp_sum(s2 * expf(m2 - M));
        if (hd_l == 2) { mh = M; ish = 1.f / S; adl = ad.z; }
        M = warp_max(m3); S = warp_sum(s3 * expf(m3 - M));
        if (hd_l == 3) { mh = M; ish = 1.f / S; adl = ad.w; }
    }

    // pass 2: weighted gather; lane owns channels [lane*8, lane*8+8)
    float acc[8];
#pragma unroll
    for (int q = 0; q < 8; q++) acc[q] = 0.f;
    for (int i = base; i < end; i++) {
        int s = g_colidx[i];
        float l = lrelu(g_asrc1[s * 4 + hd_l] + adl);
        float w = expf(l - mh) * ish;
        const float4* hp = (const float4*)(g_hfeat1 + (size_t)s * 256 + lane * 8);
        float4 u = hp[0], v = hp[1];
        acc[0] += w * u.x; acc[1] += w * u.y; acc[2] += w * u.z; acc[3] += w * u.w;
        acc[4] += w * v.x; acc[5] += w * v.y; acc[6] += w * v.z; acc[7] += w * v.w;
    }
    size_t ob = (size_t)d * 256 + lane * 8;
#pragma unroll
    for (int q = 0; q < 8; q++) {
        float o = acc[q] + b1[lane * 8 + q];
        g_out1[ob + q] = o > 0.f ? o : 0.f;   // relu folded for GAT2 input
    }
}

// ---------------- GAT2 feature GEMM: relu(out1)(N,256) @ W2(256,32) ----------------
__global__ void __launch_bounds__(256) gemm2_kernel(const float* __restrict__ W2) {
    __shared__ float W2s[256 * 32];   // 32 KB
    __shared__ float ins[16 * 256];   // 16 KB
    int tid = threadIdx.x;
    int n0 = blockIdx.x * 16;
    for (int idx = tid; idx < 256 * 32; idx += 256) W2s[idx] = W2[idx];
    for (int idx = tid; idx < 16 * 256; idx += 256) ins[idx] = g_out1[(size_t)n0 * 256 + idx];
    __syncthreads();
    int cix = tid & 31;
    int ng = tid >> 5;               // 0..7
    float acc[2] = {0.f, 0.f};
    for (int k = 0; k < 256; k++) {
        float w = W2s[k * 32 + cix];
        acc[0] += w * ins[ng * 256 + k];
        acc[1] += w * ins[(ng + 8) * 256 + k];
    }
    g_hfeat2[(size_t)(n0 + ng) * 32 + cix]     = acc[0];
    g_hfeat2[(size_t)(n0 + ng + 8) * 32 + cix] = acc[1];
}

__global__ void attn2_kernel(const float* __restrict__ as2, const float* __restrict__ ad2) {
    int n = blockIdx.x * blockDim.x + threadIdx.x;
    if (n >= NN) return;
    const float* hp = g_hfeat2 + (size_t)n * 32;
    float ss = 0.f, sd = 0.f;
    for (int cix = 0; cix < 32; cix++) {
        float v = hp[cix];
        ss += v * as2[cix];
        sd += v * ad2[cix];
    }
    g_asrc2[n] = ss;
    g_adst2[n] = sd;
}

__global__ void __launch_bounds__(256) gather2_kernel(const float* __restrict__ b2,
                                                      float* __restrict__ out) {
    int warp = (blockIdx.x * blockDim.x + threadIdx.x) >> 5;
    int lane = threadIdx.x & 31;
    if (warp >= NN) return;
    int d = warp;
    int base = g_rowptr[d], end = g_rowptr[d + 1];
    float adv = g_adst2[d];

    float m = -FLT_MAX, s = 0.f;
    for (int i = base + lane; i < end; i += 32) {
        int sidx = g_colidx[i];
        online_upd(m, s, lrelu(g_asrc2[sidx] + adv));
    }
    float M = warp_max(m);
    float S = warp_sum(s * expf(m - M));
    float ish = 1.f / S;

    float acc = 0.f;
    for (int i = base; i < end; i++) {
        int sidx = g_colidx[i];
        float l = lrelu(g_asrc2[sidx] + adv);
        float w = expf(l - M) * ish;
        acc += w * g_hfeat2[(size_t)sidx * 32 + lane];
    }
    out[(size_t)d * 32 + lane] = acc + b2[lane];
}

// ---------------- launch ----------------
extern "C" void kernel_launch(void* const* d_in, const int* in_sizes, int n_in,
                              void* d_out, int out_size) {
    const float* x     = (const float*)d_in[0];
    const int*   ei    = (const int*)d_in[1];
    const float* Wih0  = (const float*)d_in[2];
    const float* Whh0  = (const float*)d_in[3];
    const float* bih0  = (const float*)d_in[4];
    const float* bhh0  = (const float*)d_in[5];
    const float* Wih1  = (const float*)d_in[6];
    const float* Whh1  = (const float*)d_in[7];
    const float* bih1  = (const float*)d_in[8];
    const float* bhh1  = (const float*)d_in[9];
    const float* W1    = (const float*)d_in[10];
    const float* as1   = (const float*)d_in[11];
    const float* ad1   = (const float*)d_in[12];
    const float* b1    = (const float*)d_in[13];
    const float* W2    = (const float*)d_in[14];
    const float* as2   = (const float*)d_in[15];
    const float* ad2   = (const float*)d_in[16];
    const float* b2    = (const float*)d_in[17];
    float* out = (float*)d_out;

    int E = in_sizes[1] / 2;
    if (E > MAXE) E = MAXE;

    const int SMEM0 = (INDIM + HDIM) * GDIM * 4 + LROWS * (INDIM + HDIM + 4) * 4;
    const int SMEM1 = (HDIM + HDIM)  * GDIM * 4 + LROWS * (HDIM + HDIM + 4) * 4;
    cudaFuncSetAttribute(lstm_kernel<0>, cudaFuncAttributeMaxDynamicSharedMemorySize, SMEM0);
    cudaFuncSetAttribute(lstm_kernel<1>, cudaFuncAttributeMaxDynamicSharedMemorySize, SMEM1);

    const int LGRID = (NN + LROWS - 1) / LROWS;   // 139 -> single wave on 148 SMs

    // edge normalization (lstm0 placed early so ncu -s lands on it)
    detect_kernel<<<1, 32>>>(ei, E);
    norm_kernel<<<(E + 255) / 256, 256>>>(ei, E);
    init_counts_kernel<<<(NN + 255) / 256, 256>>>();

    lstm_kernel<0><<<LGRID, LTHREADS, SMEM0>>>(x, Wih0, Whh0, bih0, bhh0);

    count_kernel<<<(E + 255) / 256, 256>>>(E);
    scan_kernel<<<1, 1024>>>();
    selfloop_kernel<<<(NN + 255) / 256, 256>>>();
    fill_kernel<<<(E + 255) / 256, 256>>>(E);

    lstm_kernel<1><<<LGRID, LTHREADS, SMEM1>>>(x, Wih1, Whh1, bih1, bhh1);

    // GAT layer 1
    gemm1_kernel<<<NN / 8, 256>>>(W1);
    attn1_kernel<<<(NN * 4 + 255) / 256, 256>>>(as1, ad1);
    gather1_kernel<<<(NN * 32 + 255) / 256, 256>>>(b1);

    // GAT layer 2
    gemm2_kernel<<<NN / 16, 256>>>(W2);
    attn2_kernel<<<(NN + 255) / 256, 256>>>(as2, ad2);
    gather2_kernel<<<(NN * 32 + 255) / 256, 256>>>(b2, out);

    (void)n_in; (void)out_size;
}

// round 16
// speedup vs baseline: 2.3890x; 1.2479x over previous
#include <cuda_runtime.h>
#include <cuda_bf16.h>
#include <math.h>
#include <float.h>
#include <stdint.h>

#define NN    20000
#define TT    30
#define INDIM 32
#define HDIM  64
#define GDIM  256          // 4*H
#define MAXE  524288
#define MROWS 96           // rows per LSTM CTA (6 m-warps x 16)
#define LTHR  384          // 12 warps = 6 m x 2 u-groups

// ---------------- scratch (device globals; no allocation allowed) ----------------
static __device__ float g_h0seq[(size_t)NN * TT * HDIM];
static __device__ float g_hlast[NN * HDIM];
static __device__ float g_hfeat1[NN * GDIM];
static __device__ float g_out1[NN * GDIM];
static __device__ float g_hfeat2[NN * 32];
static __device__ float g_asrc1[NN * 4], g_adst1[NN * 4];
static __device__ float g_asrc2[NN], g_adst2[NN];
static __device__ int   g_src[MAXE], g_dst[MAXE];
static __device__ int   g_colidx[MAXE + NN];
static __device__ int   g_rowptr[NN + 1];
static __device__ int   g_cursor[NN];
static __device__ int   g_counts[NN];
static __device__ int   g_is64;

// ---------------- helpers ----------------
__device__ __forceinline__ float lrelu(float x) { return x > 0.f ? x : 0.2f * x; }
__device__ __forceinline__ float sigm_f(float x)  { return __fdividef(1.f, 1.f + __expf(-x)); }
__device__ __forceinline__ float tanh_f(float x)  { return __fdividef(2.f, 1.f + __expf(-2.f * x)) - 1.f; }

__device__ __forceinline__ float warp_max(float v) {
#pragma unroll
    for (int o = 16; o > 0; o >>= 1) v = fmaxf(v, __shfl_xor_sync(0xffffffffu, v, o));
    return v;
}
__device__ __forceinline__ float warp_sum(float v) {
#pragma unroll
    for (int o = 16; o > 0; o >>= 1) v += __shfl_xor_sync(0xffffffffu, v, o);
    return v;
}

// ---------------- HMMA primitives (sm_80+ features; no 'a' gating) ----------------
__device__ __forceinline__ uint32_t smem_u32(const void* p) {
    uint32_t a;
    asm("{ .reg .u64 t; cvta.to.shared.u64 t, %1; cvt.u32.u64 %0, t; }" : "=r"(a) : "l"(p));
    return a;
}
__device__ __forceinline__ void ldsm_x4(uint32_t* r, uint32_t addr) {
    asm volatile("ldmatrix.sync.aligned.m8n8.x4.shared.b16 {%0,%1,%2,%3}, [%4];"
                 : "=r"(r[0]), "=r"(r[1]), "=r"(r[2]), "=r"(r[3]) : "r"(addr));
}
__device__ __forceinline__ void ldsm_x2(uint32_t* r, uint32_t addr) {
    asm volatile("ldmatrix.sync.aligned.m8n8.x2.shared.b16 {%0,%1}, [%2];"
                 : "=r"(r[0]), "=r"(r[1]) : "r"(addr));
}
__device__ __forceinline__ void mma_bf16(float* c, const uint32_t* a, const uint32_t* b) {
    asm volatile("mma.sync.aligned.m16n8k16.row.col.f32.bf16.bf16.f32 "
        "{%0,%1,%2,%3}, {%4,%5,%6,%7}, {%8,%9}, {%0,%1,%2,%3};"
        : "+f"(c[0]), "+f"(c[1]), "+f"(c[2]), "+f"(c[3])
        : "r"(a[0]), "r"(a[1]), "r"(a[2]), "r"(a[3]), "r"(b[0]), "r"(b[1]));
}
__device__ __forceinline__ uint32_t pack_bf16x2(float lo, float hi) {
    uint32_t r;
    asm("cvt.rn.bf16x2.f32 %0, %1, %2;" : "=r"(r) : "f"(hi), "f"(lo));  // low half = lo
    return r;
}
__device__ __forceinline__ void bsplit(float v, float& hi, float& lo) {
    hi = __bfloat162float(__float2bfloat16(v));
    lo = v - hi;
}
// 256B-row tile with XOR-swizzled 16B chunks (col in bf16 units, row pitch 128 cols)
__device__ __forceinline__ uint32_t swz(int row, int col) {
    uint32_t kb = (uint32_t)col * 2u;
    uint32_t chunk = ((kb >> 4) ^ ((uint32_t)row & 7u)) & 15u;
    return (uint32_t)row * 256u + (chunk << 4) + (kb & 15u);
}

// smem byte offsets
#define OFF_A_HI  0
#define OFF_A_LO  24576
#define OFF_B_HI  49152
#define OFF_B_LO  114688
#define OFF_BIAS  180224
#define SMEM_MM   181248

// ---------------- edge dtype handling ----------------
__global__ void detect_kernel(const int* __restrict__ w, int E) {
    if (blockIdx.x == 0 && threadIdx.x == 0) {
        int n = E < 64 ? E : 64;
        int f = 1;
        for (int i = 0; i < n; i++)
            if (w[2 * i + 1] != 0) f = 0;
        g_is64 = f;
    }
}
__global__ void norm_kernel(const int* __restrict__ w, int E) {
    int e = blockIdx.x * blockDim.x + threadIdx.x;
    if (e >= E) return;
    if (g_is64) { g_src[e] = w[2 * e];  g_dst[e] = w[2 * (E + e)]; }
    else        { g_src[e] = w[e];      g_dst[e] = w[E + e]; }
}

// ---------------- CSR build ----------------
__global__ void init_counts_kernel() {
    int i = blockIdx.x * blockDim.x + threadIdx.x;
    if (i < NN) g_counts[i] = 1;
}
__global__ void count_kernel(int E) {
    int e = blockIdx.x * blockDim.x + threadIdx.x;
    if (e < E) atomicAdd(&g_counts[g_dst[e]], 1);
}
__global__ void scan_kernel() {
    __shared__ int part[1024];
    const int CH = 20;
    int tid = threadIdx.x;
    int b = tid * CH;
    int s = 0;
    for (int i = 0; i < CH; i++)
        if (b + i < NN) s += g_counts[b + i];
    part[tid] = s;
    __syncthreads();
    for (int off = 1; off < 1024; off <<= 1) {
        int v = (tid >= off) ? part[tid - off] : 0;
        __syncthreads();
        part[tid] += v;
        __syncthreads();
    }
    int run = part[tid] - s;
    for (int i = 0; i < CH; i++)
        if (b + i < NN) { g_rowptr[b + i] = run; run += g_counts[b + i]; }
    if (tid == 1023) g_rowptr[NN] = part[1023];
}
__global__ void selfloop_kernel() {
    int d = blockIdx.x * blockDim.x + threadIdx.x;
    if (d >= NN) return;
    int p = g_rowptr[d];
    g_colidx[p] = d;
    g_cursor[d] = p + 1;
}
__global__ void fill_kernel(int E) {
    int e = blockIdx.x * blockDim.x + threadIdx.x;
    if (e >= E) return;
    int d = g_dst[e];
    int p = atomicAdd(&g_cursor[d], 1);
    g_colidx[p] = g_src[e];
}

// ---------------- HMMA recurrent LSTM layer ----------------
// CTA = 96 rows, 384 threads = 12 warps: wm = wid>>1 (m-tile of 16 rows),
// wu = wid&1 (unit-group of 32). Warp computes, for its 16 rows, ALL 4 gates of
// its 32 units => 16 n-tiles of 8; cell state fully thread-local (16 c regs).
// A[row][k] = [x_t | h] bf16 hi/lo in swizzled smem; B[n][k] = W^T hi/lo staged once.
// Per t: acc = Ahi*Bhi + Alo*Bhi + Ahi*Blo (single fp32 accumulator, 3 mma/ntile/kstep).
template<int LAYER>
__global__ void __launch_bounds__(LTHR, 1)
lstm_mma_kernel(const float* __restrict__ xin,
                const float* __restrict__ Wih, const float* __restrict__ Whh,
                const float* __restrict__ bih, const float* __restrict__ bhh)
{
    constexpr int D  = (LAYER == 0) ? INDIM : HDIM;
    constexpr int K  = D + HDIM;      // 96 or 128
    constexpr int KS = K / 16;        // 6 or 8
    const float* src = (LAYER == 0) ? xin : g_h0seq;

    extern __shared__ char smem[];
    const uint32_t sb = smem_u32(smem);
    float* bias_s = (float*)(smem + OFF_BIAS);

    const int tid  = threadIdx.x;
    const int lane = tid & 31;
    const int wid  = tid >> 5;
    const int wm   = wid >> 1;
    const int wu   = wid & 1;
    const int mbase = wm * 16;
    const int row0  = blockIdx.x * MROWS;

    // stage B = W^T (hi/lo) once: B[n][k], k<D from Wih, else Whh
    for (int p = tid; p < 256 * (K / 2); p += LTHR) {
        int n = p / (K / 2);
        int k = (p % (K / 2)) * 2;
        float v0 = (k     < D) ? Wih[k * GDIM + n]       : Whh[(k - D) * GDIM + n];
        float v1 = (k + 1 < D) ? Wih[(k + 1) * GDIM + n] : Whh[(k + 1 - D) * GDIM + n];
        float h0, l0, h1, l1; bsplit(v0, h0, l0); bsplit(v1, h1, l1);
        uint32_t o = swz(n, k);
        *(uint32_t*)(smem + OFF_B_HI + o) = pack_bf16x2(h0, h1);
        *(uint32_t*)(smem + OFF_B_LO + o) = pack_bf16x2(l0, l1);
    }
    for (int u = tid; u < GDIM; u += LTHR) bias_s[u] = bih[u] + bhh[u];
    // zero h region of A (cols D..D+63)
    for (int p = tid; p < MROWS * 32; p += LTHR) {
        int r = p >> 5;
        int j = D + (p & 31) * 2;
        uint32_t o = swz(r, j);
        *(uint32_t*)(smem + OFF_A_HI + o) = 0u;
        *(uint32_t*)(smem + OFF_A_LO + o) = 0u;
    }

    float c[16];
#pragma unroll
    for (int i = 0; i < 16; i++) c[i] = 0.f;

    __syncthreads();

    const int lr  = lane & 15;          // ldmatrix A row within frag
    const int lk  = (lane >> 4) << 3;   // ldmatrix A k-subblock (0/8)
    const int bn  = lane & 7;           // ldmatrix B n within tile
    const int bk8 = lane & 8;           // ldmatrix B k-subblock (0/8)

    for (int t = 0; t < TT; t++) {
        // stage x_t (hi/lo) into A cols [0,D)
        for (int p = tid; p < MROWS * (D / 2); p += LTHR) {
            int r = p / (D / 2);
            int j = (p % (D / 2)) * 2;
            int grow = row0 + r;
            float v0 = 0.f, v1 = 0.f;
            if (grow < NN) {
                const float* xr = &src[((size_t)grow * TT + t) * D];
                v0 = xr[j]; v1 = xr[j + 1];
            }
            float h0, l0, h1, l1; bsplit(v0, h0, l0); bsplit(v1, h1, l1);
            uint32_t o = swz(r, j);
            *(uint32_t*)(smem + OFF_A_HI + o) = pack_bf16x2(h0, h1);
            *(uint32_t*)(smem + OFF_A_LO + o) = pack_bf16x2(l0, l1);
        }
        __syncthreads();    // x stage + prev epilogue h-writes visible

        float acc[16][4];
#pragma unroll
        for (int nt = 0; nt < 16; nt++)
#pragma unroll
            for (int j = 0; j < 4; j++) acc[nt][j] = 0.f;

#pragma unroll
        for (int ks = 0; ks < KS; ks++) {
            uint32_t ah[4], al[4];
            uint32_t aoff = swz(mbase + lr, ks * 16 + lk);
            ldsm_x4(ah, sb + OFF_A_HI + aoff);
            ldsm_x4(al, sb + OFF_A_LO + aoff);
#pragma unroll
            for (int nt = 0; nt < 16; nt++) {
                int n0 = (nt >> 2) * 64 + wu * 32 + (nt & 3) * 8;
                uint32_t boff = swz(n0 + bn, ks * 16 + bk8);
                uint32_t bh[2], bl[2];
                ldsm_x2(bh, sb + OFF_B_HI + boff);
                ldsm_x2(bl, sb + OFF_B_LO + boff);
                mma_bf16(acc[nt], ah, bh);
                mma_bf16(acc[nt], al, bh);
                mma_bf16(acc[nt], ah, bl);
            }
        }
        __syncthreads();    // all mma reads of A done before h overwrite

        // epilogue: thread owns rows {mbase+lane/4, +8}, units wu*32 + s*8 + (lane&3)*2 +{0,1}
#pragma unroll
        for (int half = 0; half < 2; half++) {
            int r = mbase + (lane >> 2) + half * 8;
            int grow = row0 + r;
            int ci = half * 2;
#pragma unroll
            for (int s = 0; s < 4; s++) {
                int u0 = wu * 32 + s * 8 + (lane & 3) * 2;
                float gi0 = acc[s][ci]        + bias_s[u0];
                float gi1 = acc[s][ci + 1]    + bias_s[u0 + 1];
                float gf0 = acc[4 + s][ci]    + bias_s[64 + u0];
                float gf1 = acc[4 + s][ci + 1]+ bias_s[64 + u0 + 1];
                float gc0 = acc[8 + s][ci]    + bias_s[128 + u0];
                float gc1 = acc[8 + s][ci + 1]+ bias_s[128 + u0 + 1];
                float go0 = acc[12 + s][ci]   + bias_s[192 + u0];
                float go1 = acc[12 + s][ci + 1]+ bias_s[192 + u0 + 1];

                float i0 = sigm_f(gi0), f0 = sigm_f(gf0), g0 = tanh_f(gc0), o0 = sigm_f(go0);
                float i1 = sigm_f(gi1), f1 = sigm_f(gf1), g1 = tanh_f(gc1), o1 = sigm_f(go1);

                int cs = (half * 4 + s) * 2;
                c[cs]     = f0 * c[cs]     + i0 * g0;
                c[cs + 1] = f1 * c[cs + 1] + i1 * g1;
                float h0 = o0 * tanh_f(c[cs]);
                float h1 = o1 * tanh_f(c[cs + 1]);

                float hh0, hl0, hh1, hl1; bsplit(h0, hh0, hl0); bsplit(h1, hh1, hl1);
                uint32_t o = swz(r, D + u0);
                *(uint32_t*)(smem + OFF_A_HI + o) = pack_bf16x2(hh0, hh1);
                *(uint32_t*)(smem + OFF_A_LO + o) = pack_bf16x2(hl0, hl1);

                if (grow < NN) {
                    if (LAYER == 0)
                        *(float2*)&g_h0seq[((size_t)grow * TT + t) * HDIM + u0] =
                            make_float2(h0, h1);
                    else if (t == TT - 1)
                        *(float2*)&g_hlast[(size_t)grow * HDIM + u0] = make_float2(h0, h1);
                }
            }
        }
    }
}

// ---------------- GAT1 feature GEMM: hlast(N,64) @ W1(64,256) ----------------
__global__ void __launch_bounds__(256) gemm1_kernel(const float* __restrict__ W1) {
    __shared__ float hs[8 * 64];
    int tid = threadIdx.x;
    int n0 = blockIdx.x * 8;
    for (int idx = tid; idx < 8 * 64; idx += 256) hs[idx] = g_hlast[(size_t)n0 * 64 + idx];
    __syncthreads();
    int j = tid;
    float acc[8];
#pragma unroll
    for (int nn = 0; nn < 8; nn++) acc[nn] = 0.f;
    for (int k = 0; k < 64; k++) {
        float w = W1[k * 256 + j];
#pragma unroll
        for (int nn = 0; nn < 8; nn++) acc[nn] += w * hs[nn * 64 + k];
    }
#pragma unroll
    for (int nn = 0; nn < 8; nn++)
        g_hfeat1[(size_t)(n0 + nn) * 256 + j] = acc[nn];
}

__global__ void attn1_kernel(const float* __restrict__ as1, const float* __restrict__ ad1) {
    int idx = blockIdx.x * blockDim.x + threadIdx.x;
    if (idx >= NN * 4) return;
    int n = idx >> 2, hd = idx & 3;
    const float* hp = g_hfeat1 + (size_t)n * 256 + hd * 64;
    float ss = 0.f, sd = 0.f;
    for (int cix = 0; cix < 64; cix++) {
        float v = hp[cix];
        ss += v * as1[hd * 64 + cix];
        sd += v * ad1[hd * 64 + cix];
    }
    g_asrc1[idx] = ss;
    g_adst1[idx] = sd;
}

__device__ __forceinline__ void online_upd(float& m, float& s, float l) {
    if (l > m) { s = s * expf(m - l) + 1.f; m = l; }
    else       { s += expf(l - m); }
}

// ---------------- GAT1 gather ----------------
__global__ void __launch_bounds__(256) gather1_kernel(const float* __restrict__ b1) {
    int warp = (blockIdx.x * blockDim.x + threadIdx.x) >> 5;
    int lane = threadIdx.x & 31;
    if (warp >= NN) return;
    int d = warp;
    int base = g_rowptr[d], end = g_rowptr[d + 1];

    float4 ad = *(const float4*)(g_adst1 + 4 * d);

    float m0 = -FLT_MAX, m1 = -FLT_MAX, m2 = -FLT_MAX, m3 = -FLT_MAX;
    float s0 = 0.f, s1 = 0.f, s2 = 0.f, s3 = 0.f;
    for (int i = base + lane; i < end; i += 32) {
        int s = g_colidx[i];
        float4 av = *(const float4*)(g_asrc1 + 4 * s);
        online_upd(m0, s0, lrelu(av.x + ad.x));
        online_upd(m1, s1, lrelu(av.y + ad.y));
        online_upd(m2, s2, lrelu(av.z + ad.z));
        online_upd(m3, s3, lrelu(av.w + ad.w));
    }
    int hd_l = lane >> 3;
    float mh = 0.f, ish = 0.f, adl = 0.f;
    {
        float M, S;
        M = warp_max(m0); S = warp_sum(s0 * expf(m0 - M));
        if (hd_l == 0) { mh = M; ish = 1.f / S; adl = ad.x; }
        M = warp_max(m1); S = warp_sum(s1 * expf(m1 - M));
        if (hd_l == 1) { mh = M; ish = 1.f / S; adl = ad.y; }
        M = warp_max(m2); S = warp_sum(s2 * expf(m2 - M));
        if (hd_l == 2) { mh = M; ish = 1.f / S; adl = ad.z; }
        M = warp_max(m3); S = warp_sum(s3 * expf(m3 - M));
        if (hd_l == 3) { mh = M; ish = 1.f / S; adl = ad.w; }
    }

    float acc[8];
#pragma unroll
    for (int q = 0; q < 8; q++) acc[q] = 0.f;
    for (int i = base; i < end; i++) {
        int s = g_colidx[i];
        float l = lrelu(g_asrc1[s * 4 + hd_l] + adl);
        float w = expf(l - mh) * ish;
        const float4* hp = (const float4*)(g_hfeat1 + (size_t)s * 256 + lane * 8);
        float4 u = hp[0], v = hp[1];
        acc[0] += w * u.x; acc[1] += w * u.y; acc[2] += w * u.z; acc[3] += w * u.w;
        acc[4] += w * v.x; acc[5] += w * v.y; acc[6] += w * v.z; acc[7] += w * v.w;
    }
    size_t ob = (size_t)d * 256 + lane * 8;
#pragma unroll
    for (int q = 0; q < 8; q++) {
        float o = acc[q] + b1[lane * 8 + q];
        g_out1[ob + q] = o > 0.f ? o : 0.f;
    }
}

// ---------------- GAT2 feature GEMM ----------------
__global__ void __launch_bounds__(256) gemm2_kernel(const float* __restrict__ W2) {
    __shared__ float W2s[256 * 32];
    __shared__ float ins[16 * 256];
    int tid = threadIdx.x;
    int n0 = blockIdx.x * 16;
    for (int idx = tid; idx < 256 * 32; idx += 256) W2s[idx] = W2[idx];
    for (int idx = tid; idx < 16 * 256; idx += 256) ins[idx] = g_out1[(size_t)n0 * 256 + idx];
    __syncthreads();
    int cix = tid & 31;
    int ng = tid >> 5;
    float acc[2] = {0.f, 0.f};
    for (int k = 0; k < 256; k++) {
        float w = W2s[k * 32 + cix];
        acc[0] += w * ins[ng * 256 + k];
        acc[1] += w * ins[(ng + 8) * 256 + k];
    }
    g_hfeat2[(size_t)(n0 + ng) * 32 + cix]     = acc[0];
    g_hfeat2[(size_t)(n0 + ng + 8) * 32 + cix] = acc[1];
}

__global__ void attn2_kernel(const float* __restrict__ as2, const float* __restrict__ ad2) {
    int n = blockIdx.x * blockDim.x + threadIdx.x;
    if (n >= NN) return;
    const float* hp = g_hfeat2 + (size_t)n * 32;
    float ss = 0.f, sd = 0.f;
    for (int cix = 0; cix < 32; cix++) {
        float v = hp[cix];
        ss += v * as2[cix];
        sd += v * ad2[cix];
    }
    g_asrc2[n] = ss;
    g_adst2[n] = sd;
}

__global__ void __launch_bounds__(256) gather2_kernel(const float* __restrict__ b2,
                                                      float* __restrict__ out) {
    int warp = (blockIdx.x * blockDim.x + threadIdx.x) >> 5;
    int lane = threadIdx.x & 31;
    if (warp >= NN) return;
    int d = warp;
    int base = g_rowptr[d], end = g_rowptr[d + 1];
    float adv = g_adst2[d];

    float m = -FLT_MAX, s = 0.f;
    for (int i = base + lane; i < end; i += 32) {
        int sidx = g_colidx[i];
        online_upd(m, s, lrelu(g_asrc2[sidx] + adv));
    }
    float M = warp_max(m);
    float S = warp_sum(s * expf(m - M));
    float ish = 1.f / S;

    float acc = 0.f;
    for (int i = base; i < end; i++) {
        int sidx = g_colidx[i];
        float l = lrelu(g_asrc2[sidx] + adv);
        float w = expf(l - M) * ish;
        acc += w * g_hfeat2[(size_t)sidx * 32 + lane];
    }
    out[(size_t)d * 32 + lane] = acc + b2[lane];
}

// ---------------- launch ----------------
extern "C" void kernel_launch(void* const* d_in, const int* in_sizes, int n_in,
                              void* d_out, int out_size) {
    const float* x     = (const float*)d_in[0];
    const int*   ei    = (const int*)d_in[1];
    const float* Wih0  = (const float*)d_in[2];
    const float* Whh0  = (const float*)d_in[3];
    const float* bih0  = (const float*)d_in[4];
    const float* bhh0  = (const float*)d_in[5];
    const float* Wih1  = (const float*)d_in[6];
    const float* Whh1  = (const float*)d_in[7];
    const float* bih1  = (const float*)d_in[8];
    const float* bhh1  = (const float*)d_in[9];
    const float* W1    = (const float*)d_in[10];
    const float* as1   = (const float*)d_in[11];
    const float* ad1   = (const float*)d_in[12];
    const float* b1    = (const float*)d_in[13];
    const float* W2    = (const float*)d_in[14];
    const float* as2   = (const float*)d_in[15];
    const float* ad2   = (const float*)d_in[16];
    const float* b2    = (const float*)d_in[17];
    float* out = (float*)d_out;

    int E = in_sizes[1] / 2;
    if (E > MAXE) E = MAXE;

    cudaFuncSetAttribute(lstm_mma_kernel<0>, cudaFuncAttributeMaxDynamicSharedMemorySize, SMEM_MM);
    cudaFuncSetAttribute(lstm_mma_kernel<1>, cudaFuncAttributeMaxDynamicSharedMemorySize, SMEM_MM);

    const int LGRID = (NN + MROWS - 1) / MROWS;   // 209

    detect_kernel<<<1, 32>>>(ei, E);
    norm_kernel<<<(E + 255) / 256, 256>>>(ei, E);
    init_counts_kernel<<<(NN + 255) / 256, 256>>>();

    lstm_mma_kernel<0><<<LGRID, LTHR, SMEM_MM>>>(x, Wih0, Whh0, bih0, bhh0);

    count_kernel<<<(E + 255) / 256, 256>>>(E);
    scan_kernel<<<1, 1024>>>();
    selfloop_kernel<<<(NN + 255) / 256, 256>>>();
    fill_kernel<<<(E + 255) / 256, 256>>>(E);

    lstm_mma_kernel<1><<<LGRID, LTHR, SMEM_MM>>>(x, Wih1, Whh1, bih1, bhh1);

    // GAT layer 1
    gemm1_kernel<<<NN / 8, 256>>>(W1);
    attn1_kernel<<<(NN * 4 + 255) / 256, 256>>>(as1, ad1);
    gather1_kernel<<<(NN * 32 + 255) / 256, 256>>>(b1);

    // GAT layer 2
    gemm2_kernel<<<NN / 16, 256>>>(W2);
    attn2_kernel<<<(NN + 255) / 256, 256>>>(as2, ad2);
    gather2_kernel<<<(NN * 32 + 255) / 256, 256>>>(b2, out);

    (void)n_in; (void)out_size;
}

// round 17
// speedup vs baseline: 3.2203x; 1.3480x over previous
#include <cuda_runtime.h>
#include <cuda_fp16.h>
#include <math.h>
#include <float.h>
#include <stdint.h>

#define NN    20000
#define TT    30
#define INDIM 32
#define HDIM  64
#define GDIM  256          // 4*H
#define MAXE  524288
#define MROWS 96           // rows per LSTM CTA (6 m-warps x 16)
#define LTHR  384          // 12 warps = 6 m x 2 u-groups

// ---------------- scratch (device globals; no allocation allowed) ----------------
static __device__ float g_h0seq[(size_t)NN * TT * HDIM];
static __device__ float g_hlast[NN * HDIM];
static __device__ float g_hfeat1[NN * GDIM];
static __device__ float g_out1[NN * GDIM];
static __device__ float g_hfeat2[NN * 32];
static __device__ float g_asrc1[NN * 4], g_adst1[NN * 4];
static __device__ float g_asrc2[NN], g_adst2[NN];
static __device__ int   g_src[MAXE], g_dst[MAXE];
static __device__ int   g_colidx[MAXE + NN];
static __device__ int   g_rowptr[NN + 1];
static __device__ int   g_cursor[NN];
static __device__ int   g_counts[NN];
static __device__ int   g_is64;

// ---------------- helpers ----------------
__device__ __forceinline__ float lrelu(float x) { return x > 0.f ? x : 0.2f * x; }
__device__ __forceinline__ float sigm_f(float x)  { return __fdividef(1.f, 1.f + __expf(-x)); }
__device__ __forceinline__ float tanh_f(float x)  { return __fdividef(2.f, 1.f + __expf(-2.f * x)) - 1.f; }

__device__ __forceinline__ float warp_max(float v) {
#pragma unroll
    for (int o = 16; o > 0; o >>= 1) v = fmaxf(v, __shfl_xor_sync(0xffffffffu, v, o));
    return v;
}
__device__ __forceinline__ float warp_sum(float v) {
#pragma unroll
    for (int o = 16; o > 0; o >>= 1) v += __shfl_xor_sync(0xffffffffu, v, o);
    return v;
}

// ---------------- HMMA primitives (sm_80+ features; no 'a' gating) ----------------
__device__ __forceinline__ uint32_t smem_u32(const void* p) {
    uint32_t a;
    asm("{ .reg .u64 t; cvta.to.shared.u64 t, %1; cvt.u32.u64 %0, t; }" : "=r"(a) : "l"(p));
    return a;
}
__device__ __forceinline__ void ldsm_x4(uint32_t* r, uint32_t addr) {
    asm volatile("ldmatrix.sync.aligned.m8n8.x4.shared.b16 {%0,%1,%2,%3}, [%4];"
                 : "=r"(r[0]), "=r"(r[1]), "=r"(r[2]), "=r"(r[3]) : "r"(addr));
}
__device__ __forceinline__ void mma_f16(float* c, const uint32_t* a, const uint32_t* b) {
    asm volatile("mma.sync.aligned.m16n8k16.row.col.f32.f16.f16.f32 "
        "{%0,%1,%2,%3}, {%4,%5,%6,%7}, {%8,%9}, {%0,%1,%2,%3};"
        : "+f"(c[0]), "+f"(c[1]), "+f"(c[2]), "+f"(c[3])
        : "r"(a[0]), "r"(a[1]), "r"(a[2]), "r"(a[3]), "r"(b[0]), "r"(b[1]));
}
__device__ __forceinline__ uint32_t pack_f16x2(float lo, float hi) {
    uint32_t r;
    asm("cvt.rn.f16x2.f32 %0, %1, %2;" : "=r"(r) : "f"(hi), "f"(lo));  // low half = lo
    return r;
}
__device__ __forceinline__ void hsplit(float v, float& hi, float& lo) {
    hi = __half2float(__float2half_rn(v));
    lo = v - hi;
}
// 256B-row tile with XOR-swizzled 16B chunks (col in fp16 units, row pitch 128 cols)
__device__ __forceinline__ uint32_t swz(int row, int col) {
    uint32_t kb = (uint32_t)col * 2u;
    uint32_t chunk = ((kb >> 4) ^ ((uint32_t)row & 7u)) & 15u;
    return (uint32_t)row * 256u + (chunk << 4) + (kb & 15u);
}

// smem byte offsets
#define OFF_A_HI  0
#define OFF_A_LO  24576
#define OFF_B_HI  49152
#define OFF_BIAS  114688
#define SMEM_MM   115712

// ---------------- edge dtype handling ----------------
__global__ void detect_kernel(const int* __restrict__ w, int E) {
    if (blockIdx.x == 0 && threadIdx.x == 0) {
        int n = E < 64 ? E : 64;
        int f = 1;
        for (int i = 0; i < n; i++)
            if (w[2 * i + 1] != 0) f = 0;
        g_is64 = f;
    }
}
__global__ void norm_kernel(const int* __restrict__ w, int E) {
    int e = blockIdx.x * blockDim.x + threadIdx.x;
    if (e >= E) return;
    if (g_is64) { g_src[e] = w[2 * e];  g_dst[e] = w[2 * (E + e)]; }
    else        { g_src[e] = w[e];      g_dst[e] = w[E + e]; }
}

// ---------------- CSR build ----------------
__global__ void init_counts_kernel() {
    int i = blockIdx.x * blockDim.x + threadIdx.x;
    if (i < NN) g_counts[i] = 1;
}
__global__ void count_kernel(int E) {
    int e = blockIdx.x * blockDim.x + threadIdx.x;
    if (e < E) atomicAdd(&g_counts[g_dst[e]], 1);
}
__global__ void scan_kernel() {
    __shared__ int part[1024];
    const int CH = 20;
    int tid = threadIdx.x;
    int b = tid * CH;
    int s = 0;
    for (int i = 0; i < CH; i++)
        if (b + i < NN) s += g_counts[b + i];
    part[tid] = s;
    __syncthreads();
    for (int off = 1; off < 1024; off <<= 1) {
        int v = (tid >= off) ? part[tid - off] : 0;
        __syncthreads();
        part[tid] += v;
        __syncthreads();
    }
    int run = part[tid] - s;
    for (int i = 0; i < CH; i++)
        if (b + i < NN) { g_rowptr[b + i] = run; run += g_counts[b + i]; }
    if (tid == 1023) g_rowptr[NN] = part[1023];
}
__global__ void selfloop_kernel() {
    int d = blockIdx.x * blockDim.x + threadIdx.x;
    if (d >= NN) return;
    int p = g_rowptr[d];
    g_colidx[p] = d;
    g_cursor[d] = p + 1;
}
__global__ void fill_kernel(int E) {
    int e = blockIdx.x * blockDim.x + threadIdx.x;
    if (e >= E) return;
    int d = g_dst[e];
    int p = atomicAdd(&g_cursor[d], 1);
    g_colidx[p] = g_src[e];
}

// ---------------- HMMA recurrent LSTM layer (fp16 2-term) ----------------
// CTA = 96 rows, 384 threads = 12 warps: wm = wid>>1 (m-tile of 16 rows),
// wu = wid&1 (unit-group of 32). Warp computes, for its 16 rows, ALL 4 gates of
// its 32 units => 16 n-tiles of 8; cell state fully thread-local (16 c regs).
// A[row][k] = [x_t | h] fp16 hi/lo in swizzled smem (A split is near-exact);
// B[n][k] = W^T fp16 hi ONLY (w rounding 2^-11 rel; error budget 1e-3).
// Per t per n-tile: acc += Ahi*Bhi; acc += Alo*Bhi (2 mma).
// B loaded with ldmatrix.x4: one load = k16 frags for a PAIR of adjacent n-tiles.
template<int LAYER>
__global__ void __launch_bounds__(LTHR, 1)
lstm_mma_kernel(const float* __restrict__ xin,
                const float* __restrict__ Wih, const float* __restrict__ Whh,
                const float* __restrict__ bih, const float* __restrict__ bhh)
{
    constexpr int D  = (LAYER == 0) ? INDIM : HDIM;
    constexpr int K  = D + HDIM;      // 96 or 128
    constexpr int KS = K / 16;        // 6 or 8
    const float* src = (LAYER == 0) ? xin : g_h0seq;

    extern __shared__ char smem[];
    const uint32_t sb = smem_u32(smem);
    float* bias_s = (float*)(smem + OFF_BIAS);

    const int tid  = threadIdx.x;
    const int lane = tid & 31;
    const int wid  = tid >> 5;
    const int wm   = wid >> 1;
    const int wu   = wid & 1;
    const int mbase = wm * 16;
    const int row0  = blockIdx.x * MROWS;

    // stage B = W^T (fp16 hi) once: B[n][k], k<D from Wih, else Whh
    for (int p = tid; p < 256 * (K / 2); p += LTHR) {
        int n = p / (K / 2);
        int k = (p % (K / 2)) * 2;
        float v0 = (k     < D) ? Wih[k * GDIM + n]       : Whh[(k - D) * GDIM + n];
        float v1 = (k + 1 < D) ? Wih[(k + 1) * GDIM + n] : Whh[(k + 1 - D) * GDIM + n];
        float h0, l0, h1, l1; hsplit(v0, h0, l0); hsplit(v1, h1, l1);
        *(uint32_t*)(smem + OFF_B_HI + swz(n, k)) = pack_f16x2(h0, h1);
    }
    for (int u = tid; u < GDIM; u += LTHR) bias_s[u] = bih[u] + bhh[u];
    // zero h region of A (cols D..D+63)
    for (int p = tid; p < MROWS * 32; p += LTHR) {
        int r = p >> 5;
        int j = D + (p & 31) * 2;
        uint32_t o = swz(r, j);
        *(uint32_t*)(smem + OFF_A_HI + o) = 0u;
        *(uint32_t*)(smem + OFF_A_LO + o) = 0u;
    }

    float c[16];
#pragma unroll
    for (int i = 0; i < 16; i++) c[i] = 0.f;

    __syncthreads();

    const int lr  = lane & 15;          // ldmatrix A row within frag
    const int lk  = (lane >> 4) << 3;   // ldmatrix A k-subblock (0/8)
    // B x4 pair-load addressing: lane -> (row, k-subblock) for 4 matrices
    const int brow = ((lane >> 4) << 3) + (lane & 7);   // 0..15 within pair
    const int bk8  = ((lane >> 3) & 1) << 3;            // 0/8

    for (int t = 0; t < TT; t++) {
        // stage x_t (hi/lo) into A cols [0,D)
        for (int p = tid; p < MROWS * (D / 2); p += LTHR) {
            int r = p / (D / 2);
            int j = (p % (D / 2)) * 2;
            int grow = row0 + r;
            float v0 = 0.f, v1 = 0.f;
            if (grow < NN) {
                const float* xr = &src[((size_t)grow * TT + t) * D];
                v0 = xr[j]; v1 = xr[j + 1];
            }
            float h0, l0, h1, l1; hsplit(v0, h0, l0); hsplit(v1, h1, l1);
            uint32_t o = swz(r, j);
            *(uint32_t*)(smem + OFF_A_HI + o) = pack_f16x2(h0, h1);
            *(uint32_t*)(smem + OFF_A_LO + o) = pack_f16x2(l0, l1);
        }
        __syncthreads();    // x stage + prev epilogue h-writes visible

        float acc[16][4];
#pragma unroll
        for (int nt = 0; nt < 16; nt++)
#pragma unroll
            for (int j = 0; j < 4; j++) acc[nt][j] = 0.f;

#pragma unroll
        for (int ks = 0; ks < KS; ks++) {
            uint32_t ah[4], al[4];
            uint32_t aoff = swz(mbase + lr, ks * 16 + lk);
            ldsm_x4(ah, sb + OFF_A_HI + aoff);
            ldsm_x4(al, sb + OFF_A_LO + aoff);
#pragma unroll
            for (int p = 0; p < 8; p++) {
                // pair p covers n-tiles nt0=(p>>1)*4... mapping: gate g=p>>1, subpair sp=p&1
                int g  = p >> 1;
                int sp = p & 1;
                int nt0 = g * 4 + sp * 2;
                int n0p = g * 64 + wu * 32 + sp * 16;
                uint32_t b4[4];
                ldsm_x4(b4, sb + OFF_B_HI + swz(n0p + brow, ks * 16 + bk8));
                mma_f16(acc[nt0],     ah, b4);
                mma_f16(acc[nt0],     al, b4);
                mma_f16(acc[nt0 + 1], ah, b4 + 2);
                mma_f16(acc[nt0 + 1], al, b4 + 2);
            }
        }
        __syncthreads();    // all mma reads of A done before h overwrite

        // epilogue: thread owns rows {mbase+lane/4, +8}, units wu*32 + s*8 + (lane&3)*2 +{0,1}
#pragma unroll
        for (int half = 0; half < 2; half++) {
            int r = mbase + (lane >> 2) + half * 8;
            int grow = row0 + r;
            int ci = half * 2;
#pragma unroll
            for (int s = 0; s < 4; s++) {
                int u0 = wu * 32 + s * 8 + (lane & 3) * 2;
                float gi0 = acc[s][ci]         + bias_s[u0];
                float gi1 = acc[s][ci + 1]     + bias_s[u0 + 1];
                float gf0 = acc[4 + s][ci]     + bias_s[64 + u0];
                float gf1 = acc[4 + s][ci + 1] + bias_s[64 + u0 + 1];
                float gc0 = acc[8 + s][ci]     + bias_s[128 + u0];
                float gc1 = acc[8 + s][ci + 1] + bias_s[128 + u0 + 1];
                float go0 = acc[12 + s][ci]    + bias_s[192 + u0];
                float go1 = acc[12 + s][ci + 1]+ bias_s[192 + u0 + 1];

                float i0 = sigm_f(gi0), f0 = sigm_f(gf0), g0 = tanh_f(gc0), o0 = sigm_f(go0);
                float i1 = sigm_f(gi1), f1 = sigm_f(gf1), g1 = tanh_f(gc1), o1 = sigm_f(go1);

                int cs = (half * 4 + s) * 2;
                c[cs]     = f0 * c[cs]     + i0 * g0;
                c[cs + 1] = f1 * c[cs + 1] + i1 * g1;
                float h0 = o0 * tanh_f(c[cs]);
                float h1 = o1 * tanh_f(c[cs + 1]);

                float hh0, hl0, hh1, hl1; hsplit(h0, hh0, hl0); hsplit(h1, hh1, hl1);
                uint32_t o = swz(r, D + u0);
                *(uint32_t*)(smem + OFF_A_HI + o) = pack_f16x2(hh0, hh1);
                *(uint32_t*)(smem + OFF_A_LO + o) = pack_f16x2(hl0, hl1);

                if (grow < NN) {
                    if (LAYER == 0)
                        *(float2*)&g_h0seq[((size_t)grow * TT + t) * HDIM + u0] =
                            make_float2(h0, h1);
                    else if (t == TT - 1)
                        *(float2*)&g_hlast[(size_t)grow * HDIM + u0] = make_float2(h0, h1);
                }
            }
        }
    }
}

// ---------------- GAT1 feature GEMM: hlast(N,64) @ W1(64,256) ----------------
__global__ void __launch_bounds__(256) gemm1_kernel(const float* __restrict__ W1) {
    __shared__ float hs[8 * 64];
    int tid = threadIdx.x;
    int n0 = blockIdx.x * 8;
    for (int idx = tid; idx < 8 * 64; idx += 256) hs[idx] = g_hlast[(size_t)n0 * 64 + idx];
    __syncthreads();
    int j = tid;
    float acc[8];
#pragma unroll
    for (int nn = 0; nn < 8; nn++) acc[nn] = 0.f;
    for (int k = 0; k < 64; k++) {
        float w = W1[k * 256 + j];
#pragma unroll
        for (int nn = 0; nn < 8; nn++) acc[nn] += w * hs[nn * 64 + k];
    }
#pragma unroll
    for (int nn = 0; nn < 8; nn++)
        g_hfeat1[(size_t)(n0 + nn) * 256 + j] = acc[nn];
}

__global__ void attn1_kernel(const float* __restrict__ as1, const float* __restrict__ ad1) {
    int idx = blockIdx.x * blockDim.x + threadIdx.x;
    if (idx >= NN * 4) return;
    int n = idx >> 2, hd = idx & 3;
    const float* hp = g_hfeat1 + (size_t)n * 256 + hd * 64;
    float ss = 0.f, sd = 0.f;
    for (int cix = 0; cix < 64; cix++) {
        float v = hp[cix];
        ss += v * as1[hd * 64 + cix];
        sd += v * ad1[hd * 64 + cix];
    }
    g_asrc1[idx] = ss;
    g_adst1[idx] = sd;
}

__device__ __forceinline__ void online_upd(float& m, float& s, float l) {
    if (l > m) { s = s * expf(m - l) + 1.f; m = l; }
    else       { s += expf(l - m); }
}

// ---------------- GAT1 gather ----------------
__global__ void __launch_bounds__(256) gather1_kernel(const float* __restrict__ b1) {
    int warp = (blockIdx.x * blockDim.x + threadIdx.x) >> 5;
    int lane = threadIdx.x & 31;
    if (warp >= NN) return;
    int d = warp;
    int base = g_rowptr[d], end = g_rowptr[d + 1];

    float4 ad = *(const float4*)(g_adst1 + 4 * d);

    float m0 = -FLT_MAX, m1 = -FLT_MAX, m2 = -FLT_MAX, m3 = -FLT_MAX;
    float s0 = 0.f, s1 = 0.f, s2 = 0.f, s3 = 0.f;
    for (int i = base + lane; i < end; i += 32) {
        int s = g_colidx[i];
        float4 av = *(const float4*)(g_asrc1 + 4 * s);
        online_upd(m0, s0, lrelu(av.x + ad.x));
        online_upd(m1, s1, lrelu(av.y + ad.y));
        online_upd(m2, s2, lrelu(av.z + ad.z));
        online_upd(m3, s3, lrelu(av.w + ad.w));
    }
    int hd_l = lane >> 3;
    float mh = 0.f, ish = 0.f, adl = 0.f;
    {
        float M, S;
        M = warp_max(m0); S = warp_sum(s0 * expf(m0 - M));
        if (hd_l == 0) { mh = M; ish = 1.f / S; adl = ad.x; }
        M = warp_max(m1); S = warp_sum(s1 * expf(m1 - M));
        if (hd_l == 1) { mh = M; ish = 1.f / S; adl = ad.y; }
        M = warp_max(m2); S = warp_sum(s2 * expf(m2 - M));
        if (hd_l == 2) { mh = M; ish = 1.f / S; adl = ad.z; }
        M = warp_max(m3); S = warp_sum(s3 * expf(m3 - M));
        if (hd_l == 3) { mh = M; ish = 1.f / S; adl = ad.w; }
    }

    float acc[8];
#pragma unroll
    for (int q = 0; q < 8; q++) acc[q] = 0.f;
    for (int i = base; i < end; i++) {
        int s = g_colidx[i];
        float l = lrelu(g_asrc1[s * 4 + hd_l] + adl);
        float w = expf(l - mh) * ish;
        const float4* hp = (const float4*)(g_hfeat1 + (size_t)s * 256 + lane * 8);
        float4 u = hp[0], v = hp[1];
        acc[0] += w * u.x; acc[1] += w * u.y; acc[2] += w * u.z; acc[3] += w * u.w;
        acc[4] += w * v.x; acc[5] += w * v.y; acc[6] += w * v.z; acc[7] += w * v.w;
    }
    size_t ob = (size_t)d * 256 + lane * 8;
#pragma unroll
    for (int q = 0; q < 8; q++) {
        float o = acc[q] + b1[lane * 8 + q];
        g_out1[ob + q] = o > 0.f ? o : 0.f;
    }
}

// ---------------- GAT2 feature GEMM ----------------
__global__ void __launch_bounds__(256) gemm2_kernel(const float* __restrict__ W2) {
    __shared__ float W2s[256 * 32];
    __shared__ float ins[16 * 256];
    int tid = threadIdx.x;
    int n0 = blockIdx.x * 16;
    for (int idx = tid; idx < 256 * 32; idx += 256) W2s[idx] = W2[idx];
    for (int idx = tid; idx < 16 * 256; idx += 256) ins[idx] = g_out1[(size_t)n0 * 256 + idx];
    __syncthreads();
    int cix = tid & 31;
    int ng = tid >> 5;
    float acc[2] = {0.f, 0.f};
    for (int k = 0; k < 256; k++) {
        float w = W2s[k * 32 + cix];
        acc[0] += w * ins[ng * 256 + k];
        acc[1] += w * ins[(ng + 8) * 256 + k];
    }
    g_hfeat2[(size_t)(n0 + ng) * 32 + cix]     = acc[0];
    g_hfeat2[(size_t)(n0 + ng + 8) * 32 + cix] = acc[1];
}

__global__ void attn2_kernel(const float* __restrict__ as2, const float* __restrict__ ad2) {
    int n = blockIdx.x * blockDim.x + threadIdx.x;
    if (n >= NN) return;
    const float* hp = g_hfeat2 + (size_t)n * 32;
    float ss = 0.f, sd = 0.f;
    for (int cix = 0; cix < 32; cix++) {
        float v = hp[cix];
        ss += v * as2[cix];
        sd += v * ad2[cix];
    }
    g_asrc2[n] = ss;
    g_adst2[n] = sd;
}

__global__ void __launch_bounds__(256) gather2_kernel(const float* __restrict__ b2,
                                                      float* __restrict__ out) {
    int warp = (blockIdx.x * blockDim.x + threadIdx.x) >> 5;
    int lane = threadIdx.x & 31;
    if (warp >= NN) return;
    int d = warp;
    int base = g_rowptr[d], end = g_rowptr[d + 1];
    float adv = g_adst2[d];

    float m = -FLT_MAX, s = 0.f;
    for (int i = base + lane; i < end; i += 32) {
        int sidx = g_colidx[i];
        online_upd(m, s, lrelu(g_asrc2[sidx] + adv));
    }
    float M = warp_max(m);
    float S = warp_sum(s * expf(m - M));
    float ish = 1.f / S;

    float acc = 0.f;
    for (int i = base; i < end; i++) {
        int sidx = g_colidx[i];
        float l = lrelu(g_asrc2[sidx] + adv);
        float w = expf(l - M) * ish;
        acc += w * g_hfeat2[(size_t)sidx * 32 + lane];
    }
    out[(size_t)d * 32 + lane] = acc + b2[lane];
}

// ---------------- launch ----------------
extern "C" void kernel_launch(void* const* d_in, const int* in_sizes, int n_in,
                              void* d_out, int out_size) {
    const float* x     = (const float*)d_in[0];
    const int*   ei    = (const int*)d_in[1];
    const float* Wih0  = (const float*)d_in[2];
    const float* Whh0  = (const float*)d_in[3];
    const float* bih0  = (const float*)d_in[4];
    const float* bhh0  = (const float*)d_in[5];
    const float* Wih1  = (const float*)d_in[6];
    const float* Whh1  = (const float*)d_in[7];
    const float* bih1  = (const float*)d_in[8];
    const float* bhh1  = (const float*)d_in[9];
    const float* W1    = (const float*)d_in[10];
    const float* as1   = (const float*)d_in[11];
    const float* ad1   = (const float*)d_in[12];
    const float* b1    = (const float*)d_in[13];
    const float* W2    = (const float*)d_in[14];
    const float* as2   = (const float*)d_in[15];
    const float* ad2   = (const float*)d_in[16];
    const float* b2    = (const float*)d_in[17];
    float* out = (float*)d_out;

    int E = in_sizes[1] / 2;
    if (E > MAXE) E = MAXE;

    cudaFuncSetAttribute(lstm_mma_kernel<0>, cudaFuncAttributeMaxDynamicSharedMemorySize, SMEM_MM);
    cudaFuncSetAttribute(lstm_mma_kernel<1>, cudaFuncAttributeMaxDynamicSharedMemorySize, SMEM_MM);

    const int LGRID = (NN + MROWS - 1) / MROWS;   // 209

    detect_kernel<<<1, 32>>>(ei, E);
    norm_kernel<<<(E + 255) / 256, 256>>>(ei, E);
    init_counts_kernel<<<(NN + 255) / 256, 256>>>();

    lstm_mma_kernel<0><<<LGRID, LTHR, SMEM_MM>>>(x, Wih0, Whh0, bih0, bhh0);

    count_kernel<<<(E + 255) / 256, 256>>>(E);
    scan_kernel<<<1, 1024>>>();
    selfloop_kernel<<<(NN + 255) / 256, 256>>>();
    fill_kernel<<<(E + 255) / 256, 256>>>(E);

    lstm_mma_kernel<1><<<LGRID, LTHR, SMEM_MM>>>(x, Wih1, Whh1, bih1, bhh1);

    // GAT layer 1
    gemm1_kernel<<<NN / 8, 256>>>(W1);
    attn1_kernel<<<(NN * 4 + 255) / 256, 256>>>(as1, ad1);
    gather1_kernel<<<(NN * 32 + 255) / 256, 256>>>(b1);

    // GAT layer 2
    gemm2_kernel<<<NN / 16, 256>>>(W2);
    attn2_kernel<<<(NN + 255) / 256, 256>>>(as2, ad2);
    gather2_kernel<<<(NN * 32 + 255) / 256, 256>>>(b2, out);

    (void)n_in; (void)out_size;
}